// round 12
// baseline (speedup 1.0000x reference)
#include <cuda_runtime.h>
#include <cuda_fp16.h>

#define G_N   8192
#define NH    8
#define HDIM  64
#define AD    512
#define GFDIM 32
#define CIMG  256
#define IMG   64
#define NPIX  (IMG*IMG)
#define KPTS  12
#define SIGC  9.21f
#define NGH   (G_N * NH)

typedef unsigned long long u64t;

// ---- packed f32x2 helpers ----
__device__ __forceinline__ u64t ffma2(u64t a, u64t b, u64t c) {
    u64t d; asm("fma.rn.f32x2 %0, %1, %2, %3;" : "=l"(d) : "l"(a), "l"(b), "l"(c));
    return d;
}
__device__ __forceinline__ u64t fmul2(u64t a, u64t b) {
    u64t d; asm("mul.rn.f32x2 %0, %1, %2;" : "=l"(d) : "l"(a), "l"(b)); return d;
}
__device__ __forceinline__ u64t fadd2(u64t a, u64t b) {
    u64t d; asm("add.rn.f32x2 %0, %1, %2;" : "=l"(d) : "l"(a), "l"(b)); return d;
}
__device__ __forceinline__ u64t splat2(float x) {
    u64t d; asm("mov.b64 %0, {%1, %1};" : "=l"(d) : "f"(x)); return d;
}
__device__ __forceinline__ u64t pk2(float x, float y) {
    u64t d; asm("mov.b64 %0, {%1, %2};" : "=l"(d) : "f"(x), "f"(y)); return d;
}
__device__ __forceinline__ float2 unpk(u64t a) {
    float2 r; asm("mov.b64 {%0, %1}, %2;" : "=f"(r.x), "=f"(r.y) : "l"(a)); return r;
}
__device__ __forceinline__ u64t shflx64(u64t v, int m) {
    float2 f = unpk(v);
    f.x = __shfl_xor_sync(0xffffffffu, f.x, m);
    f.y = __shfl_xor_sync(0xffffffffu, f.y, m);
    return pk2(f.x, f.y);
}

// Scratch (~65 MB, L2-resident working set)
__device__ __half g_kv[NH * NPIX * 128];     // 8MB   [h][pix][lane16: k4|v4]
__device__ __half g_q[G_N * 3 * AD];         // 25MB  fp16 queries
__device__ int2   g_pts[NGH * KPTS];         // 6.3MB {pix<<4|fl, half2(wx1,wy1)}
__device__ __half g_attn[G_N * 3 * AD];      // 25MB  attention out fp16

__constant__ float c_fix[18] = {0,0,0, 1,0,0, 0,1,0, 0,0,1, -1,0,0, 0,-1,0};

// ---------------------------------------------------------------------------
// K1: kv maps -> fp16 g_kv (unchanged)
// ---------------------------------------------------------------------------
__global__ __launch_bounds__(256) void kv_gemm(
    const float* __restrict__ img, const float* __restrict__ Wk,
    const float* __restrict__ Wv)
{
    const int m0 = blockIdx.x * 64;
    const int n0 = blockIdx.y * 128;
    __shared__ float As[16][64];
    __shared__ float Bks[16][128];
    __shared__ float Bvs[16][128];
    const int t  = threadIdx.x;
    const int tx = t & 15, ty = t >> 4;

    u64t ak2[4][4], av2[4][4];
#pragma unroll
    for (int i = 0; i < 4; i++)
#pragma unroll
        for (int j = 0; j < 4; j++) { ak2[i][j] = 0ull; av2[i][j] = 0ull; }

    for (int c0 = 0; c0 < CIMG; c0 += 16) {
        *(float4*)&As[ty][tx * 4] =
            *(const float4*)(img + (size_t)(c0 + ty) * NPIX + m0 + tx * 4);
#pragma unroll
        for (int rep = 0; rep < 2; rep++) {
            int idx = t + rep * 256;
            int nn  = idx >> 2;
            int kk4 = (idx & 3) * 4;
            float4 wk = *(const float4*)(Wk + (size_t)(n0 + nn) * CIMG + c0 + kk4);
            float4 wv = *(const float4*)(Wv + (size_t)(n0 + nn) * CIMG + c0 + kk4);
            Bks[kk4 + 0][nn] = wk.x; Bks[kk4 + 1][nn] = wk.y;
            Bks[kk4 + 2][nn] = wk.z; Bks[kk4 + 3][nn] = wk.w;
            Bvs[kk4 + 0][nn] = wv.x; Bvs[kk4 + 1][nn] = wv.y;
            Bvs[kk4 + 2][nn] = wv.z; Bvs[kk4 + 3][nn] = wv.w;
        }
        __syncthreads();
#pragma unroll
        for (int kk = 0; kk < 16; kk++) {
            float4 a4 = *(float4*)&As[kk][ty * 4];
            ulonglong2 bkl = *(ulonglong2*)&Bks[kk][tx * 4];
            ulonglong2 bkh = *(ulonglong2*)&Bks[kk][tx * 4 + 64];
            ulonglong2 bvl = *(ulonglong2*)&Bvs[kk][tx * 4];
            ulonglong2 bvh = *(ulonglong2*)&Bvs[kk][tx * 4 + 64];
            u64t bk[4] = {bkl.x, bkl.y, bkh.x, bkh.y};
            u64t bv[4] = {bvl.x, bvl.y, bvh.x, bvh.y};
            float a[4] = {a4.x, a4.y, a4.z, a4.w};
#pragma unroll
            for (int i = 0; i < 4; i++) {
                u64t as = splat2(a[i]);
#pragma unroll
                for (int j = 0; j < 4; j++) {
                    ak2[i][j] = ffma2(as, bk[j], ak2[i][j]);
                    av2[i][j] = ffma2(as, bv[j], av2[i][j]);
                }
            }
        }
        __syncthreads();
    }
#pragma unroll
    for (int i = 0; i < 4; i++) {
        int m = m0 + ty * 4 + i;
#pragma unroll
        for (int q = 0; q < 2; q++) {
            int hh = (n0 >> 6) + q;
            __half* dst = g_kv + ((size_t)(hh * NPIX + m)) * 128 + tx * 8;
            float2 k0 = unpk(ak2[i][q*2+0]), k1 = unpk(ak2[i][q*2+1]);
            float2 v0 = unpk(av2[i][q*2+0]), v1 = unpk(av2[i][q*2+1]);
            union { uint4 u; __half2 h2[4]; } p;
            p.h2[0] = __floats2half2_rn(k0.x, k0.y);
            p.h2[1] = __floats2half2_rn(k1.x, k1.y);
            p.h2[2] = __floats2half2_rn(v0.x, v0.y);
            p.h2[3] = __floats2half2_rn(v1.x, v1.y);
            *(uint4*)dst = p.u;
        }
    }
}

// ---------------------------------------------------------------------------
// K2: q = features @ Wq -> fp16 g_q (unchanged)
// ---------------------------------------------------------------------------
__global__ __launch_bounds__(256) void q_gemm(
    const float* __restrict__ feat, const float* __restrict__ Wq)
{
    const int r0 = blockIdx.x * 64;
    const int n0 = blockIdx.y * 256;
    __shared__ float Fs[64][32];
    __shared__ float Ws[32][256];
    const int t = threadIdx.x;
#pragma unroll
    for (int rep = 0; rep < 8; rep++) {
        int idx = t + rep * 256;
        Fs[idx >> 5][idx & 31] = feat[(size_t)(r0 + (idx >> 5)) * GFDIM + (idx & 31)];
    }
#pragma unroll
    for (int rep = 0; rep < 8; rep++) {
        int idx = t + rep * 256;
        int k = idx >> 6, n4 = (idx & 63) << 2;
        *(float4*)&Ws[k][n4] = *(const float4*)(Wq + (size_t)k * AD + n0 + n4);
    }
    __syncthreads();

    const int tc = t & 15, tr = t >> 4;
    u64t acc2[4][8];
#pragma unroll
    for (int i = 0; i < 4; i++)
#pragma unroll
        for (int j = 0; j < 8; j++) acc2[i][j] = 0ull;

#pragma unroll
    for (int k = 0; k < 32; k++) {
        u64t fs[4];
#pragma unroll
        for (int i = 0; i < 4; i++) fs[i] = splat2(Fs[tr * 4 + i][k]);
        u64t w[8];
#pragma unroll
        for (int q = 0; q < 4; q++) {
            ulonglong2 w2 = *(ulonglong2*)&Ws[k][q * 64 + tc * 4];
            w[q*2+0] = w2.x; w[q*2+1] = w2.y;
        }
#pragma unroll
        for (int i = 0; i < 4; i++)
#pragma unroll
            for (int j = 0; j < 8; j++) acc2[i][j] = ffma2(fs[i], w[j], acc2[i][j]);
    }
#pragma unroll
    for (int i = 0; i < 4; i++) {
        int r = r0 + tr * 4 + i;
#pragma unroll
        for (int q = 0; q < 4; q++) {
            float2 a = unpk(acc2[i][q*2+0]), b = unpk(acc2[i][q*2+1]);
            union { uint2 u; __half2 h2[2]; } cv;
            cv.h2[0] = __floats2half2_rn(a.x, a.y);
            cv.h2[1] = __floats2half2_rn(b.x, b.y);
            *(uint2*)&g_q[(size_t)r * AD + n0 + q * 64 + tc * 4] = cv.u;
        }
    }
}

// ---------------------------------------------------------------------------
// K3: sigpp (unchanged)
// ---------------------------------------------------------------------------
__global__ __launch_bounds__(256) void sigpp(
    const float* __restrict__ means, const float* __restrict__ scales,
    const float* __restrict__ rots, const float* __restrict__ transforms,
    const float* __restrict__ proj, const float* __restrict__ W_off,
    const float* __restrict__ b_off)
{
    const int r0 = blockIdx.x * 64;
    __shared__ float Xs[64][69];
    __shared__ float Ws[67][20];
    __shared__ float bs[20];
    __shared__ float sh_learn[64][18];
    __shared__ float sh_rot[8][9];
    __shared__ float sh_scl[8][3];
    __shared__ float sh_proj[12];
    const int t = threadIdx.x;

    for (int idx = t; idx < 64 * 64; idx += 256) {
        int rl = idx >> 6, c = idx & 63;
        int r = r0 + rl, g = r >> 3, h = r & 7;
        const __half* q = g_q + (size_t)(g * 3) * AD + h * HDIM + c;
        Xs[rl][3 + c] = (__half2float(q[0]) + __half2float(q[AD])
                       + __half2float(q[2 * AD])) * (1.f / 3.f);
    }
    if (t < 64) {
        int r = r0 + t, g = r >> 3;
        float mx = means[g*3], my = means[g*3+1], mz = means[g*3+2];
        const float* T = transforms + (size_t)g * 16;
        Xs[t][0] = T[0]*mx + T[1]*my + T[2] *mz + T[3];
        Xs[t][1] = T[4]*mx + T[5]*my + T[6] *mz + T[7];
        Xs[t][2] = T[8]*mx + T[9]*my + T[10]*mz + T[11];
    }
    for (int idx = t; idx < 67 * 20; idx += 256) {
        int i = idx / 20, o = idx % 20;
        Ws[i][o] = (o < 18) ? W_off[i * 18 + o] : 0.f;
    }
    if (t < 20) bs[t] = (t < 18) ? b_off[t] : 0.f;
    if (t < 12) sh_proj[t] = proj[t];
    if (t >= 32 && t < 40) {
        int gl = t - 32, g = (r0 >> 3) + gl;
        float qw = rots[g*4+0], qx = rots[g*4+1], qy = rots[g*4+2], qz = rots[g*4+3];
        float qn = rsqrtf(qw*qw + qx*qx + qy*qy + qz*qz);
        qw *= qn; qx *= qn; qy *= qn; qz *= qn;
        sh_rot[gl][0] = 1.f-2.f*(qy*qy+qz*qz); sh_rot[gl][1] = 2.f*(qx*qy-qw*qz);
        sh_rot[gl][2] = 2.f*(qx*qz+qw*qy);     sh_rot[gl][3] = 2.f*(qx*qy+qw*qz);
        sh_rot[gl][4] = 1.f-2.f*(qx*qx+qz*qz); sh_rot[gl][5] = 2.f*(qy*qz-qw*qx);
        sh_rot[gl][6] = 2.f*(qx*qz-qw*qy);     sh_rot[gl][7] = 2.f*(qy*qz+qw*qx);
        sh_rot[gl][8] = 1.f-2.f*(qx*qx+qy*qy);
        sh_scl[gl][0] = scales[g*3+0];
        sh_scl[gl][1] = scales[g*3+1];
        sh_scl[gl][2] = scales[g*3+2];
    }
    __syncthreads();

    {
        const int rl = t & 63, og = t >> 6;
        const int obase = og * 5;
        float acc[5] = {0.f, 0.f, 0.f, 0.f, 0.f};
        for (int i = 0; i < 67; i++) {
            float x = Xs[rl][i];
#pragma unroll
            for (int u = 0; u < 5; u++) acc[u] += x * Ws[i][obase + u];
        }
        const int on = (og == 3) ? 3 : 5;
        for (int u = 0; u < on; u++) {
            float z = acc[u] + bs[obase + u];
            z = fminf(fmaxf(z, -SIGC), SIGC);
            sh_learn[rl][obase + u] = 1.f / (1.f + __expf(-z)) - 0.5f;
        }
    }
    __syncthreads();

#pragma unroll
    for (int it = 0; it < 3; it++) {
        int id = t + it * 256;
        int rl = id / KPTS, kp = id - rl * KPTS;
        int gl = rl >> 3;
        float s0, s1, s2;
        if (kp < 6) { s0 = c_fix[kp*3+0]; s1 = c_fix[kp*3+1]; s2 = c_fix[kp*3+2]; }
        else { const float* lp = &sh_learn[rl][(kp - 6) * 3];
               s0 = lp[0]; s1 = lp[1]; s2 = lp[2]; }
        float v0 = s0 * sh_scl[gl][0], v1 = s1 * sh_scl[gl][1], v2 = s2 * sh_scl[gl][2];
        const float* R = sh_rot[gl];
        float px = R[0]*v0 + R[3]*v1 + R[6]*v2 + Xs[rl][0];
        float py = R[1]*v0 + R[4]*v1 + R[7]*v2 + Xs[rl][1];
        float pz = R[2]*v0 + R[5]*v1 + R[8]*v2 + Xs[rl][2];
        float p0 = sh_proj[0]*px + sh_proj[1]*py + sh_proj[2] *pz + sh_proj[3];
        float p1 = sh_proj[4]*px + sh_proj[5]*py + sh_proj[6] *pz + sh_proj[7];
        float p2 = sh_proj[8]*px + sh_proj[9]*py + sh_proj[10]*pz + sh_proj[11];
        float zz = fmaxf(p2, 1e-5f);
        float u = p0 / zz, v = p1 / zz;
        const float lim = 0.9999f * (float)IMG;
        float xf = fminf(fmaxf(u, 0.f), lim) - 0.5f;
        float yf = fminf(fmaxf(v, 0.f), lim) - 0.5f;
        float fx0 = floorf(xf), fy0 = floorf(yf);
        float wx1 = xf - fx0, wy1 = yf - fy0;
        int x0 = (int)fx0, y0 = (int)fy0;
        int pix = y0 * IMG + x0;
        int vx0 = (unsigned)x0       < IMG;
        int vx1 = (unsigned)(x0 + 1) < IMG;
        int vy0 = (unsigned)y0       < IMG;
        int vy1 = (unsigned)(y0 + 1) < IMG;
        int fl = (vy0 & vx0) | ((vy0 & vx1) << 1) | ((vy1 & vx0) << 2) | ((vy1 & vx1) << 3);
        union { __half2 h; int i; } wv;
        wv.h = __floats2half2_rn(wx1, wy1);
        g_pts[(size_t)(r0 + rl) * KPTS + kp] = make_int2((pix << 4) | fl, wv.i);
    }
}

// ---------------------------------------------------------------------------
// K4: gather_attn — no prefetch double-buffer; 5 blocks/SM for occupancy.
// ---------------------------------------------------------------------------
__global__ __launch_bounds__(256, 5) void gather_attn()
{
    const int g    = blockIdx.x;
    const int tid  = threadIdx.x;
    const int h    = tid >> 5;
    const int lane = tid & 31;
    const int l    = lane & 15;
    const int half = lane >> 4;

    const __half* qr = g_q + (size_t)(g * 3) * AD + h * HDIM + l * 4;
    u64t Q0a, Q0b, Q1a, Q1b, Q2a, Q2b;
    {
        union { uint2 u; __half2 h2[2]; } c;
        float2 a, b;
        c.u = *(const uint2*)(qr);
        a = __half22float2(c.h2[0]); b = __half22float2(c.h2[1]);
        Q0a = pk2(a.x, a.y); Q0b = pk2(b.x, b.y);
        c.u = *(const uint2*)(qr + AD);
        a = __half22float2(c.h2[0]); b = __half22float2(c.h2[1]);
        Q1a = pk2(a.x, a.y); Q1b = pk2(b.x, b.y);
        c.u = *(const uint2*)(qr + 2 * AD);
        a = __half22float2(c.h2[0]); b = __half22float2(c.h2[1]);
        Q2a = pk2(a.x, a.y); Q2b = pk2(b.x, b.y);
    }

    int2 pt;
    { int kpl = lane < KPTS ? lane : KPTS - 1;
      pt = g_pts[(size_t)(g * NH + h) * KPTS + kpl]; }

    const char* kvb = (const char*)g_kv + (size_t)h * NPIX * 256 + l * 16;

    float s0v = 0.f, s1v = 0.f, s2v = 0.f;
    u64t o0a = 0ull, o0b = 0ull, o1a = 0ull, o1b = 0ull, o2a = 0ull, o2b = 0ull;

#pragma unroll
    for (int i = 0; i < KPTS / 2; i++) {
        const int src = 2 * i + half;
        int w0 = __shfl_sync(0xffffffffu, pt.x, src);
        int w1 = __shfl_sync(0xffffffffu, pt.y, src);
        int bf = w0 & 15;
        union { int i; __half2 h; } wu; wu.i = w1;
        float2 wxy = __half22float2(wu.h);
        float cwx1 = wxy.x, cwy1 = wxy.y;
        const char* p = kvb + ((long)(w0 >> 4) << 8);
        uint4 T0 = make_uint4(0,0,0,0), T1 = T0, T2 = T0, T3 = T0;
        if (bf & 1) T0 = *(const uint4*)(p);
        if (bf & 2) T1 = *(const uint4*)(p + 256);
        if (bf & 4) T2 = *(const uint4*)(p + IMG * 256);
        if (bf & 8) T3 = *(const uint4*)(p + IMG * 256 + 256);

        float wx0 = 1.f - cwx1, wy0 = 1.f - cwy1;
        __half2 hw00 = __float2half2_rn(wx0  * wy0);
        __half2 hw01 = __float2half2_rn(cwx1 * wy0);
        __half2 hw10 = __float2half2_rn(wx0  * cwy1);
        __half2 hw11 = __float2half2_rn(cwx1 * cwy1);
        union { uint4 u; __half2 h2[4]; } A, B, C, D;
        A.u = T0; B.u = T1; C.u = T2; D.u = T3;
        __half2 hk0 = __hfma2(hw00, A.h2[0], __hfma2(hw01, B.h2[0],
                      __hfma2(hw10, C.h2[0], __hmul2(hw11, D.h2[0]))));
        __half2 hk1 = __hfma2(hw00, A.h2[1], __hfma2(hw01, B.h2[1],
                      __hfma2(hw10, C.h2[1], __hmul2(hw11, D.h2[1]))));
        __half2 hv0 = __hfma2(hw00, A.h2[2], __hfma2(hw01, B.h2[2],
                      __hfma2(hw10, C.h2[2], __hmul2(hw11, D.h2[2]))));
        __half2 hv1 = __hfma2(hw00, A.h2[3], __hfma2(hw01, B.h2[3],
                      __hfma2(hw10, C.h2[3], __hmul2(hw11, D.h2[3]))));
        float2 kf0 = __half22float2(hk0), kf1 = __half22float2(hk1);
        float2 vf0 = __half22float2(hv0), vf1 = __half22float2(hv1);
        u64t aka = pk2(kf0.x, kf0.y), akb = pk2(kf1.x, kf1.y);
        u64t ava = pk2(vf0.x, vf0.y), avb = pk2(vf1.x, vf1.y);

        float2 p0 = unpk(ffma2(Q0a, aka, fmul2(Q0b, akb)));
        float2 p1 = unpk(ffma2(Q1a, aka, fmul2(Q1b, akb)));
        float2 p2 = unpk(ffma2(Q2a, aka, fmul2(Q2b, akb)));
        float d0 = p0.x + p0.y, d1 = p1.x + p1.y, d2 = p2.x + p2.y;
#pragma unroll
        for (int off = 8; off > 0; off >>= 1) {
            d0 += __shfl_xor_sync(0xffffffffu, d0, off);
            d1 += __shfl_xor_sync(0xffffffffu, d1, off);
            d2 += __shfl_xor_sync(0xffffffffu, d2, off);
        }
        float e0 = __expf(d0 * 0.125f);
        float e1 = __expf(d1 * 0.125f);
        float e2 = __expf(d2 * 0.125f);
        s0v += e0; s1v += e1; s2v += e2;
        u64t e0p = splat2(e0), e1p = splat2(e1), e2p = splat2(e2);
        o0a = ffma2(e0p, ava, o0a); o0b = ffma2(e0p, avb, o0b);
        o1a = ffma2(e1p, ava, o1a); o1b = ffma2(e1p, avb, o1b);
        o2a = ffma2(e2p, ava, o2a); o2b = ffma2(e2p, avb, o2b);
    }

    o0a = fadd2(o0a, shflx64(o0a, 16)); o0b = fadd2(o0b, shflx64(o0b, 16));
    o1a = fadd2(o1a, shflx64(o1a, 16)); o1b = fadd2(o1b, shflx64(o1b, 16));
    o2a = fadd2(o2a, shflx64(o2a, 16)); o2b = fadd2(o2b, shflx64(o2b, 16));
    s0v += __shfl_xor_sync(0xffffffffu, s0v, 16);
    s1v += __shfl_xor_sync(0xffffffffu, s1v, 16);
    s2v += __shfl_xor_sync(0xffffffffu, s2v, 16);

    if (half == 0) {
        __half* orow = g_attn + (size_t)(g * 3) * AD + h * HDIM + l * 4;
        u64t i0 = splat2(1.f / s0v), i1 = splat2(1.f / s1v), i2 = splat2(1.f / s2v);
        union { uint2 u; __half2 h2[2]; } cv;
        float2 a, b;
        a = unpk(fmul2(o0a, i0)); b = unpk(fmul2(o0b, i0));
        cv.h2[0] = __floats2half2_rn(a.x, a.y); cv.h2[1] = __floats2half2_rn(b.x, b.y);
        *(uint2*)(orow) = cv.u;
        a = unpk(fmul2(o1a, i1)); b = unpk(fmul2(o1b, i1));
        cv.h2[0] = __floats2half2_rn(a.x, a.y); cv.h2[1] = __floats2half2_rn(b.x, b.y);
        *(uint2*)(orow + AD) = cv.u;
        a = unpk(fmul2(o2a, i2)); b = unpk(fmul2(o2b, i2));
        cv.h2[0] = __floats2half2_rn(a.x, a.y); cv.h2[1] = __floats2half2_rn(b.x, b.y);
        *(uint2*)(orow + 2 * AD) = cv.u;
    }
}

// ---------------------------------------------------------------------------
// K5: out_gemm (unchanged)
// ---------------------------------------------------------------------------
__global__ __launch_bounds__(256) void out_gemm(
    const float* __restrict__ Wout, const float* __restrict__ b_out,
    const float* __restrict__ feat, float* __restrict__ out)
{
    const int r0 = blockIdx.x * 64;
    __shared__ float Xs[32][66];
    __shared__ float Ws[32][32];
    const int t = threadIdx.x;
    const int c = t & 31, rb = (t >> 5) * 8;
    u64t acc2[4] = {0ull, 0ull, 0ull, 0ull};

    for (int k0 = 0; k0 < AD; k0 += 32) {
#pragma unroll
        for (int rep = 0; rep < 8; rep++) {
            int idx = t + rep * 256;
            int row = idx >> 5, kc = idx & 31;
            Xs[kc][row] = __half2float(
                g_attn[(size_t)(r0 + row) * AD + k0 + kc]);
        }
#pragma unroll
        for (int rep = 0; rep < 4; rep++) {
            int idx = t + rep * 256;
            Ws[idx >> 5][idx & 31] = Wout[(size_t)(k0 + (idx >> 5)) * GFDIM + (idx & 31)];
        }
        __syncthreads();
#pragma unroll
        for (int kk = 0; kk < 32; kk++) {
            u64t w = splat2(Ws[kk][c]);
#pragma unroll
            for (int i = 0; i < 4; i++)
                acc2[i] = ffma2(w, *(const u64t*)&Xs[kk][rb + 2 * i], acc2[i]);
        }
        __syncthreads();
    }
    float b = b_out[c];
#pragma unroll
    for (int i = 0; i < 4; i++) {
        float2 r = unpk(acc2[i]);
        int row0 = r0 + rb + 2 * i;
        out[(size_t)row0 * GFDIM + c]       = r.x + b + feat[(size_t)row0 * GFDIM + c];
        out[(size_t)(row0 + 1) * GFDIM + c] = r.y + b + feat[(size_t)(row0 + 1) * GFDIM + c];
    }
}

// ---------------------------------------------------------------------------
extern "C" void kernel_launch(void* const* d_in, const int* in_sizes, int n_in,
                              void* d_out, int out_size)
{
    const float* means      = (const float*)d_in[0];
    const float* scales     = (const float*)d_in[1];
    const float* rotations  = (const float*)d_in[2];
    const float* features   = (const float*)d_in[3];
    const float* transforms = (const float*)d_in[4];
    const float* projection = (const float*)d_in[5];
    const float* image_feat = (const float*)d_in[6];
    const float* Wq         = (const float*)d_in[7];
    const float* Wk         = (const float*)d_in[8];
    const float* Wv         = (const float*)d_in[9];
    const float* W_off      = (const float*)d_in[10];
    const float* b_off      = (const float*)d_in[11];
    const float* Wout       = (const float*)d_in[12];
    const float* b_out      = (const float*)d_in[13];
    float* out = (float*)d_out;

    kv_gemm<<<dim3(NPIX / 64, AD / 128), 256>>>(image_feat, Wk, Wv);
    q_gemm<<<dim3(G_N * 3 / 64, AD / 256), 256>>>(features, Wq);
    sigpp<<<NGH / 64, 256>>>(means, scales, rotations, transforms,
                             projection, W_off, b_off);
    gather_attn<<<G_N, 256>>>();
    out_gemm<<<G_N * 3 / 64, 256>>>(Wout, b_out, features, out);
}

// round 13
// speedup vs baseline: 1.0467x; 1.0467x over previous
#include <cuda_runtime.h>
#include <cuda_fp16.h>

#define G_N   8192
#define NH    8
#define HDIM  64
#define AD    512
#define GFDIM 32
#define CIMG  256
#define IMG   64
#define NPIX  (IMG*IMG)
#define KPTS  12
#define SIGC  9.21f
#define NGH   (G_N * NH)

typedef unsigned long long u64t;

// ---- packed f32x2 helpers ----
__device__ __forceinline__ u64t ffma2(u64t a, u64t b, u64t c) {
    u64t d; asm("fma.rn.f32x2 %0, %1, %2, %3;" : "=l"(d) : "l"(a), "l"(b), "l"(c));
    return d;
}
__device__ __forceinline__ u64t splat2(float x) {
    u64t d; asm("mov.b64 %0, {%1, %1};" : "=l"(d) : "f"(x)); return d;
}
__device__ __forceinline__ float2 unpk(u64t a) {
    float2 r; asm("mov.b64 {%0, %1}, %2;" : "=f"(r.x), "=f"(r.y) : "l"(a)); return r;
}
__device__ __forceinline__ __half2 uint_as_h2(unsigned u) {
    union { unsigned u; __half2 h; } c; c.u = u; return c.h;
}
__device__ __forceinline__ unsigned h2_as_uint(__half2 h) {
    union { unsigned u; __half2 h; } c; c.h = h; return c.u;
}
__device__ __forceinline__ __half2 h2shflx(__half2 v, int m) {
    return uint_as_h2(__shfl_xor_sync(0xffffffffu, h2_as_uint(v), m));
}

// Scratch (~65 MB, L2-resident working set)
__device__ __half g_kv[NH * NPIX * 128];     // 8MB   [h][pix][lane16: k4|v4]
__device__ __half g_q[G_N * 3 * AD];         // 25MB  fp16 queries, PRESCALED by 1/8
__device__ int2   g_pts[NGH * KPTS];         // 6.3MB {pix<<4|fl, half2(wx1,wy1)}
__device__ __half g_attn[G_N * 3 * AD];      // 25MB  attention out fp16

__constant__ float c_fix[18] = {0,0,0, 1,0,0, 0,1,0, 0,0,1, -1,0,0, 0,-1,0};

// ---------------------------------------------------------------------------
// K1: kv maps -> fp16 g_kv (unchanged)
// ---------------------------------------------------------------------------
__global__ __launch_bounds__(256) void kv_gemm(
    const float* __restrict__ img, const float* __restrict__ Wk,
    const float* __restrict__ Wv)
{
    const int m0 = blockIdx.x * 64;
    const int n0 = blockIdx.y * 128;
    __shared__ float As[16][64];
    __shared__ float Bks[16][128];
    __shared__ float Bvs[16][128];
    const int t  = threadIdx.x;
    const int tx = t & 15, ty = t >> 4;

    u64t ak2[4][4], av2[4][4];
#pragma unroll
    for (int i = 0; i < 4; i++)
#pragma unroll
        for (int j = 0; j < 4; j++) { ak2[i][j] = 0ull; av2[i][j] = 0ull; }

    for (int c0 = 0; c0 < CIMG; c0 += 16) {
        *(float4*)&As[ty][tx * 4] =
            *(const float4*)(img + (size_t)(c0 + ty) * NPIX + m0 + tx * 4);
#pragma unroll
        for (int rep = 0; rep < 2; rep++) {
            int idx = t + rep * 256;
            int nn  = idx >> 2;
            int kk4 = (idx & 3) * 4;
            float4 wk = *(const float4*)(Wk + (size_t)(n0 + nn) * CIMG + c0 + kk4);
            float4 wv = *(const float4*)(Wv + (size_t)(n0 + nn) * CIMG + c0 + kk4);
            Bks[kk4 + 0][nn] = wk.x; Bks[kk4 + 1][nn] = wk.y;
            Bks[kk4 + 2][nn] = wk.z; Bks[kk4 + 3][nn] = wk.w;
            Bvs[kk4 + 0][nn] = wv.x; Bvs[kk4 + 1][nn] = wv.y;
            Bvs[kk4 + 2][nn] = wv.z; Bvs[kk4 + 3][nn] = wv.w;
        }
        __syncthreads();
#pragma unroll
        for (int kk = 0; kk < 16; kk++) {
            float4 a4 = *(float4*)&As[kk][ty * 4];
            ulonglong2 bkl = *(ulonglong2*)&Bks[kk][tx * 4];
            ulonglong2 bkh = *(ulonglong2*)&Bks[kk][tx * 4 + 64];
            ulonglong2 bvl = *(ulonglong2*)&Bvs[kk][tx * 4];
            ulonglong2 bvh = *(ulonglong2*)&Bvs[kk][tx * 4 + 64];
            u64t bk[4] = {bkl.x, bkl.y, bkh.x, bkh.y};
            u64t bv[4] = {bvl.x, bvl.y, bvh.x, bvh.y};
            float a[4] = {a4.x, a4.y, a4.z, a4.w};
#pragma unroll
            for (int i = 0; i < 4; i++) {
                u64t as = splat2(a[i]);
#pragma unroll
                for (int j = 0; j < 4; j++) {
                    ak2[i][j] = ffma2(as, bk[j], ak2[i][j]);
                    av2[i][j] = ffma2(as, bv[j], av2[i][j]);
                }
            }
        }
        __syncthreads();
    }
#pragma unroll
    for (int i = 0; i < 4; i++) {
        int m = m0 + ty * 4 + i;
#pragma unroll
        for (int q = 0; q < 2; q++) {
            int hh = (n0 >> 6) + q;
            __half* dst = g_kv + ((size_t)(hh * NPIX + m)) * 128 + tx * 8;
            float2 k0 = unpk(ak2[i][q*2+0]), k1 = unpk(ak2[i][q*2+1]);
            float2 v0 = unpk(av2[i][q*2+0]), v1 = unpk(av2[i][q*2+1]);
            union { uint4 u; __half2 h2[4]; } p;
            p.h2[0] = __floats2half2_rn(k0.x, k0.y);
            p.h2[1] = __floats2half2_rn(k1.x, k1.y);
            p.h2[2] = __floats2half2_rn(v0.x, v0.y);
            p.h2[3] = __floats2half2_rn(v1.x, v1.y);
            *(uint4*)dst = p.u;
        }
    }
}

// ---------------------------------------------------------------------------
// K2: q = (features * 0.125) @ Wq -> fp16 g_q (q/8, exact power-of-2 scale)
// ---------------------------------------------------------------------------
__global__ __launch_bounds__(256) void q_gemm(
    const float* __restrict__ feat, const float* __restrict__ Wq)
{
    const int r0 = blockIdx.x * 64;
    const int n0 = blockIdx.y * 256;
    __shared__ float Fs[64][32];
    __shared__ float Ws[32][256];
    const int t = threadIdx.x;
#pragma unroll
    for (int rep = 0; rep < 8; rep++) {
        int idx = t + rep * 256;
        Fs[idx >> 5][idx & 31] =
            feat[(size_t)(r0 + (idx >> 5)) * GFDIM + (idx & 31)] * 0.125f;
    }
#pragma unroll
    for (int rep = 0; rep < 8; rep++) {
        int idx = t + rep * 256;
        int k = idx >> 6, n4 = (idx & 63) << 2;
        *(float4*)&Ws[k][n4] = *(const float4*)(Wq + (size_t)k * AD + n0 + n4);
    }
    __syncthreads();

    const int tc = t & 15, tr = t >> 4;
    u64t acc2[4][8];
#pragma unroll
    for (int i = 0; i < 4; i++)
#pragma unroll
        for (int j = 0; j < 8; j++) acc2[i][j] = 0ull;

#pragma unroll
    for (int k = 0; k < 32; k++) {
        u64t fs[4];
#pragma unroll
        for (int i = 0; i < 4; i++) fs[i] = splat2(Fs[tr * 4 + i][k]);
        u64t w[8];
#pragma unroll
        for (int q = 0; q < 4; q++) {
            ulonglong2 w2 = *(ulonglong2*)&Ws[k][q * 64 + tc * 4];
            w[q*2+0] = w2.x; w[q*2+1] = w2.y;
        }
#pragma unroll
        for (int i = 0; i < 4; i++)
#pragma unroll
            for (int j = 0; j < 8; j++) acc2[i][j] = ffma2(fs[i], w[j], acc2[i][j]);
    }
#pragma unroll
    for (int i = 0; i < 4; i++) {
        int r = r0 + tr * 4 + i;
#pragma unroll
        for (int q = 0; q < 4; q++) {
            float2 a = unpk(acc2[i][q*2+0]), b = unpk(acc2[i][q*2+1]);
            union { uint2 u; __half2 h2[2]; } cv;
            cv.h2[0] = __floats2half2_rn(a.x, a.y);
            cv.h2[1] = __floats2half2_rn(b.x, b.y);
            *(uint2*)&g_q[(size_t)r * AD + n0 + q * 64 + tc * 4] = cv.u;
        }
    }
}

// ---------------------------------------------------------------------------
// K3: sigpp — OffsetNet + point projection.  qmean factor is 8/3 to undo the
//     1/8 prescale in g_q (both powers of 2 -> exact).
// ---------------------------------------------------------------------------
__global__ __launch_bounds__(256) void sigpp(
    const float* __restrict__ means, const float* __restrict__ scales,
    const float* __restrict__ rots, const float* __restrict__ transforms,
    const float* __restrict__ proj, const float* __restrict__ W_off,
    const float* __restrict__ b_off)
{
    const int r0 = blockIdx.x * 64;
    __shared__ float Xs[64][69];
    __shared__ float Ws[67][20];
    __shared__ float bs[20];
    __shared__ float sh_learn[64][18];
    __shared__ float sh_rot[8][9];
    __shared__ float sh_scl[8][3];
    __shared__ float sh_proj[12];
    const int t = threadIdx.x;

    for (int idx = t; idx < 64 * 64; idx += 256) {
        int rl = idx >> 6, c = idx & 63;
        int r = r0 + rl, g = r >> 3, h = r & 7;
        const __half* q = g_q + (size_t)(g * 3) * AD + h * HDIM + c;
        Xs[rl][3 + c] = (__half2float(q[0]) + __half2float(q[AD])
                       + __half2float(q[2 * AD])) * (8.f / 3.f);
    }
    if (t < 64) {
        int r = r0 + t, g = r >> 3;
        float mx = means[g*3], my = means[g*3+1], mz = means[g*3+2];
        const float* T = transforms + (size_t)g * 16;
        Xs[t][0] = T[0]*mx + T[1]*my + T[2] *mz + T[3];
        Xs[t][1] = T[4]*mx + T[5]*my + T[6] *mz + T[7];
        Xs[t][2] = T[8]*mx + T[9]*my + T[10]*mz + T[11];
    }
    for (int idx = t; idx < 67 * 20; idx += 256) {
        int i = idx / 20, o = idx % 20;
        Ws[i][o] = (o < 18) ? W_off[i * 18 + o] : 0.f;
    }
    if (t < 20) bs[t] = (t < 18) ? b_off[t] : 0.f;
    if (t < 12) sh_proj[t] = proj[t];
    if (t >= 32 && t < 40) {
        int gl = t - 32, g = (r0 >> 3) + gl;
        float qw = rots[g*4+0], qx = rots[g*4+1], qy = rots[g*4+2], qz = rots[g*4+3];
        float qn = rsqrtf(qw*qw + qx*qx + qy*qy + qz*qz);
        qw *= qn; qx *= qn; qy *= qn; qz *= qn;
        sh_rot[gl][0] = 1.f-2.f*(qy*qy+qz*qz); sh_rot[gl][1] = 2.f*(qx*qy-qw*qz);
        sh_rot[gl][2] = 2.f*(qx*qz+qw*qy);     sh_rot[gl][3] = 2.f*(qx*qy+qw*qz);
        sh_rot[gl][4] = 1.f-2.f*(qx*qx+qz*qz); sh_rot[gl][5] = 2.f*(qy*qz-qw*qx);
        sh_rot[gl][6] = 2.f*(qx*qz-qw*qy);     sh_rot[gl][7] = 2.f*(qy*qz+qw*qx);
        sh_rot[gl][8] = 1.f-2.f*(qx*qx+qy*qy);
        sh_scl[gl][0] = scales[g*3+0];
        sh_scl[gl][1] = scales[g*3+1];
        sh_scl[gl][2] = scales[g*3+2];
    }
    __syncthreads();

    {
        const int rl = t & 63, og = t >> 6;
        const int obase = og * 5;
        float acc[5] = {0.f, 0.f, 0.f, 0.f, 0.f};
        for (int i = 0; i < 67; i++) {
            float x = Xs[rl][i];
#pragma unroll
            for (int u = 0; u < 5; u++) acc[u] += x * Ws[i][obase + u];
        }
        const int on = (og == 3) ? 3 : 5;
        for (int u = 0; u < on; u++) {
            float z = acc[u] + bs[obase + u];
            z = fminf(fmaxf(z, -SIGC), SIGC);
            sh_learn[rl][obase + u] = 1.f / (1.f + __expf(-z)) - 0.5f;
        }
    }
    __syncthreads();

#pragma unroll
    for (int it = 0; it < 3; it++) {
        int id = t + it * 256;
        int rl = id / KPTS, kp = id - rl * KPTS;
        int gl = rl >> 3;
        float s0, s1, s2;
        if (kp < 6) { s0 = c_fix[kp*3+0]; s1 = c_fix[kp*3+1]; s2 = c_fix[kp*3+2]; }
        else { const float* lp = &sh_learn[rl][(kp - 6) * 3];
               s0 = lp[0]; s1 = lp[1]; s2 = lp[2]; }
        float v0 = s0 * sh_scl[gl][0], v1 = s1 * sh_scl[gl][1], v2 = s2 * sh_scl[gl][2];
        const float* R = sh_rot[gl];
        float px = R[0]*v0 + R[3]*v1 + R[6]*v2 + Xs[rl][0];
        float py = R[1]*v0 + R[4]*v1 + R[7]*v2 + Xs[rl][1];
        float pz = R[2]*v0 + R[5]*v1 + R[8]*v2 + Xs[rl][2];
        float p0 = sh_proj[0]*px + sh_proj[1]*py + sh_proj[2] *pz + sh_proj[3];
        float p1 = sh_proj[4]*px + sh_proj[5]*py + sh_proj[6] *pz + sh_proj[7];
        float p2 = sh_proj[8]*px + sh_proj[9]*py + sh_proj[10]*pz + sh_proj[11];
        float zz = fmaxf(p2, 1e-5f);
        float u = p0 / zz, v = p1 / zz;
        const float lim = 0.9999f * (float)IMG;
        float xf = fminf(fmaxf(u, 0.f), lim) - 0.5f;
        float yf = fminf(fmaxf(v, 0.f), lim) - 0.5f;
        float fx0 = floorf(xf), fy0 = floorf(yf);
        float wx1 = xf - fx0, wy1 = yf - fy0;
        int x0 = (int)fx0, y0 = (int)fy0;
        int pix = y0 * IMG + x0;
        int vx0 = (unsigned)x0       < IMG;
        int vx1 = (unsigned)(x0 + 1) < IMG;
        int vy0 = (unsigned)y0       < IMG;
        int vy1 = (unsigned)(y0 + 1) < IMG;
        int fl = (vy0 & vx0) | ((vy0 & vx1) << 1) | ((vy1 & vx0) << 2) | ((vy1 & vx1) << 3);
        union { __half2 h; int i; } wv;
        wv.h = __floats2half2_rn(wx1, wy1);
        g_pts[(size_t)(r0 + rl) * KPTS + kp] = make_int2((pix << 4) | fl, wv.i);
    }
}

// ---------------------------------------------------------------------------
// K4: gather_attn — full half2 datapath (dots, reduce, v-accum in __half2),
//     q prescaled by 1/8, R10-style depth-2 prefetch pipeline.
// ---------------------------------------------------------------------------
__global__ __launch_bounds__(256) void gather_attn()
{
    const int g    = blockIdx.x;
    const int tid  = threadIdx.x;
    const int h    = tid >> 5;
    const int lane = tid & 31;
    const int l    = lane & 15;
    const int half = lane >> 4;

    // q/8 channels 4l..4l+3 per token, kept in half2 (no conversion)
    const __half* qr = g_q + (size_t)(g * 3) * AD + h * HDIM + l * 4;
    uint2 q0u = *(const uint2*)(qr);
    uint2 q1u = *(const uint2*)(qr + AD);
    uint2 q2u = *(const uint2*)(qr + 2 * AD);
    __half2 Q0a = uint_as_h2(q0u.x), Q0b = uint_as_h2(q0u.y);
    __half2 Q1a = uint_as_h2(q1u.x), Q1b = uint_as_h2(q1u.y);
    __half2 Q2a = uint_as_h2(q2u.x), Q2b = uint_as_h2(q2u.y);

    int2 pt;
    { int kpl = lane < KPTS ? lane : KPTS - 1;
      pt = g_pts[(size_t)(g * NH + h) * KPTS + kpl]; }

    const char* kvb = (const char*)g_kv + (size_t)h * NPIX * 256 + l * 16;

    float s0v = 0.f, s1v = 0.f, s2v = 0.f;
    const __half2 hz = __float2half2_rn(0.f);
    __half2 o0a = hz, o0b = hz, o1a = hz, o1b = hz, o2a = hz, o2b = hz;

    // prologue: fetch iteration 0
    uint4 T0, T1, T2, T3;
    float cwx1, cwy1;
    {
        int w0 = __shfl_sync(0xffffffffu, pt.x, half);
        int w1 = __shfl_sync(0xffffffffu, pt.y, half);
        int bf = w0 & 15;
        float2 w = __half22float2(uint_as_h2((unsigned)w1));
        cwx1 = w.x; cwy1 = w.y;
        const char* p = kvb + ((long)(w0 >> 4) << 8);
        T0 = T1 = T2 = T3 = make_uint4(0, 0, 0, 0);
        if (bf & 1) T0 = *(const uint4*)(p);
        if (bf & 2) T1 = *(const uint4*)(p + 256);
        if (bf & 4) T2 = *(const uint4*)(p + IMG * 256);
        if (bf & 8) T3 = *(const uint4*)(p + IMG * 256 + 256);
    }

#pragma unroll
    for (int i = 0; i < KPTS / 2; i++) {
        uint4 N0, N1, N2, N3;
        float nwx1 = 0.f, nwy1 = 0.f;
        N0 = N1 = N2 = N3 = make_uint4(0, 0, 0, 0);
        if (i < KPTS / 2 - 1) {      // prefetch next iteration
            int src = 2 * (i + 1) + half;
            int w0 = __shfl_sync(0xffffffffu, pt.x, src);
            int w1 = __shfl_sync(0xffffffffu, pt.y, src);
            int bf = w0 & 15;
            float2 w = __half22float2(uint_as_h2((unsigned)w1));
            nwx1 = w.x; nwy1 = w.y;
            const char* p = kvb + ((long)(w0 >> 4) << 8);
            if (bf & 1) N0 = *(const uint4*)(p);
            if (bf & 2) N1 = *(const uint4*)(p + 256);
            if (bf & 4) N2 = *(const uint4*)(p + IMG * 256);
            if (bf & 8) N3 = *(const uint4*)(p + IMG * 256 + 256);
        }

        float wx0 = 1.f - cwx1, wy0 = 1.f - cwy1;
        __half2 hw00 = __float2half2_rn(wx0  * wy0);
        __half2 hw01 = __float2half2_rn(cwx1 * wy0);
        __half2 hw10 = __float2half2_rn(wx0  * cwy1);
        __half2 hw11 = __float2half2_rn(cwx1 * cwy1);
        union { uint4 u; __half2 h2[4]; } A, B, C, D;
        A.u = T0; B.u = T1; C.u = T2; D.u = T3;
        __half2 hk0 = __hfma2(hw00, A.h2[0], __hfma2(hw01, B.h2[0],
                      __hfma2(hw10, C.h2[0], __hmul2(hw11, D.h2[0]))));
        __half2 hk1 = __hfma2(hw00, A.h2[1], __hfma2(hw01, B.h2[1],
                      __hfma2(hw10, C.h2[1], __hmul2(hw11, D.h2[1]))));
        __half2 hv0 = __hfma2(hw00, A.h2[2], __hfma2(hw01, B.h2[2],
                      __hfma2(hw10, C.h2[2], __hmul2(hw11, D.h2[2]))));
        __half2 hv1 = __hfma2(hw00, A.h2[3], __hfma2(hw01, B.h2[3],
                      __hfma2(hw10, C.h2[3], __hmul2(hw11, D.h2[3]))));

        // dots in half2 (q prescaled: result is the score directly)
        __half2 d0h = __hfma2(Q0a, hk0, __hmul2(Q0b, hk1));
        __half2 d1h = __hfma2(Q1a, hk0, __hmul2(Q1b, hk1));
        __half2 d2h = __hfma2(Q2a, hk0, __hmul2(Q2b, hk1));
#pragma unroll
        for (int off = 8; off > 0; off >>= 1) {
            d0h = __hadd2(d0h, h2shflx(d0h, off));
            d1h = __hadd2(d1h, h2shflx(d1h, off));
            d2h = __hadd2(d2h, h2shflx(d2h, off));
        }
        float2 f0 = __half22float2(d0h);
        float2 f1 = __half22float2(d1h);
        float2 f2 = __half22float2(d2h);
        float e0 = __expf(f0.x + f0.y);
        float e1 = __expf(f1.x + f1.y);
        float e2 = __expf(f2.x + f2.y);
        s0v += e0; s1v += e1; s2v += e2;
        __half2 e0h = __float2half2_rn(e0);
        __half2 e1h = __float2half2_rn(e1);
        __half2 e2h = __float2half2_rn(e2);
        o0a = __hfma2(e0h, hv0, o0a); o0b = __hfma2(e0h, hv1, o0b);
        o1a = __hfma2(e1h, hv0, o1a); o1b = __hfma2(e1h, hv1, o1b);
        o2a = __hfma2(e2h, hv0, o2a); o2b = __hfma2(e2h, hv1, o2b);

        T0 = N0; T1 = N1; T2 = N2; T3 = N3;
        cwx1 = nwx1; cwy1 = nwy1;
    }

    // combine the two halves (each summed 6 points over identical channels)
    o0a = __hadd2(o0a, h2shflx(o0a, 16)); o0b = __hadd2(o0b, h2shflx(o0b, 16));
    o1a = __hadd2(o1a, h2shflx(o1a, 16)); o1b = __hadd2(o1b, h2shflx(o1b, 16));
    o2a = __hadd2(o2a, h2shflx(o2a, 16)); o2b = __hadd2(o2b, h2shflx(o2b, 16));
    s0v += __shfl_xor_sync(0xffffffffu, s0v, 16);
    s1v += __shfl_xor_sync(0xffffffffu, s1v, 16);
    s2v += __shfl_xor_sync(0xffffffffu, s2v, 16);

    if (half == 0) {
        __half* orow = g_attn + (size_t)(g * 3) * AD + h * HDIM + l * 4;
        __half2 i0 = __float2half2_rn(1.f / s0v);
        __half2 i1 = __float2half2_rn(1.f / s1v);
        __half2 i2 = __float2half2_rn(1.f / s2v);
        uint2 st;
        st.x = h2_as_uint(__hmul2(o0a, i0)); st.y = h2_as_uint(__hmul2(o0b, i0));
        *(uint2*)(orow) = st;
        st.x = h2_as_uint(__hmul2(o1a, i1)); st.y = h2_as_uint(__hmul2(o1b, i1));
        *(uint2*)(orow + AD) = st;
        st.x = h2_as_uint(__hmul2(o2a, i2)); st.y = h2_as_uint(__hmul2(o2b, i2));
        *(uint2*)(orow + 2 * AD) = st;
    }
}

// ---------------------------------------------------------------------------
// K5: out_gemm (unchanged)
// ---------------------------------------------------------------------------
__global__ __launch_bounds__(256) void out_gemm(
    const float* __restrict__ Wout, const float* __restrict__ b_out,
    const float* __restrict__ feat, float* __restrict__ out)
{
    const int r0 = blockIdx.x * 64;
    __shared__ float Xs[32][66];
    __shared__ float Ws[32][32];
    const int t = threadIdx.x;
    const int c = t & 31, rb = (t >> 5) * 8;
    u64t acc2[4] = {0ull, 0ull, 0ull, 0ull};

    for (int k0 = 0; k0 < AD; k0 += 32) {
#pragma unroll
        for (int rep = 0; rep < 8; rep++) {
            int idx = t + rep * 256;
            int row = idx >> 5, kc = idx & 31;
            Xs[kc][row] = __half2float(
                g_attn[(size_t)(r0 + row) * AD + k0 + kc]);
        }
#pragma unroll
        for (int rep = 0; rep < 4; rep++) {
            int idx = t + rep * 256;
            Ws[idx >> 5][idx & 31] = Wout[(size_t)(k0 + (idx >> 5)) * GFDIM + (idx & 31)];
        }
        __syncthreads();
#pragma unroll
        for (int kk = 0; kk < 32; kk++) {
            u64t w = splat2(Ws[kk][c]);
#pragma unroll
            for (int i = 0; i < 4; i++)
                acc2[i] = ffma2(w, *(const u64t*)&Xs[kk][rb + 2 * i], acc2[i]);
        }
        __syncthreads();
    }
    float b = b_out[c];
#pragma unroll
    for (int i = 0; i < 4; i++) {
        float2 r = unpk(acc2[i]);
        int row0 = r0 + rb + 2 * i;
        out[(size_t)row0 * GFDIM + c]       = r.x + b + feat[(size_t)row0 * GFDIM + c];
        out[(size_t)(row0 + 1) * GFDIM + c] = r.y + b + feat[(size_t)(row0 + 1) * GFDIM + c];
    }
}

// ---------------------------------------------------------------------------
extern "C" void kernel_launch(void* const* d_in, const int* in_sizes, int n_in,
                              void* d_out, int out_size)
{
    const float* means      = (const float*)d_in[0];
    const float* scales     = (const float*)d_in[1];
    const float* rotations  = (const float*)d_in[2];
    const float* features   = (const float*)d_in[3];
    const float* transforms = (const float*)d_in[4];
    const float* projection = (const float*)d_in[5];
    const float* image_feat = (const float*)d_in[6];
    const float* Wq         = (const float*)d_in[7];
    const float* Wk         = (const float*)d_in[8];
    const float* Wv         = (const float*)d_in[9];
    const float* W_off      = (const float*)d_in[10];
    const float* b_off      = (const float*)d_in[11];
    const float* Wout       = (const float*)d_in[12];
    const float* b_out      = (const float*)d_in[13];
    float* out = (float*)d_out;

    kv_gemm<<<dim3(NPIX / 64, AD / 128), 256>>>(image_feat, Wk, Wv);
    q_gemm<<<dim3(G_N * 3 / 64, AD / 256), 256>>>(features, Wq);
    sigpp<<<NGH / 64, 256>>>(means, scales, rotations, transforms,
                             projection, W_off, b_off);
    gather_attn<<<G_N, 256>>>();
    out_gemm<<<G_N * 3 / 64, 256>>>(Wout, b_out, features, out);
}

// round 14
// speedup vs baseline: 1.2278x; 1.1730x over previous
#include <cuda_runtime.h>
#include <cuda_fp16.h>

#define G_N   8192
#define NH    8
#define HDIM  64
#define AD    512
#define GFDIM 32
#define CIMG  256
#define IMG   64
#define NPIX  (IMG*IMG)
#define KPTS  12
#define SIGC  9.21f
#define NGH   (G_N * NH)

typedef unsigned long long u64t;

// ---- packed f32x2 helpers ----
__device__ __forceinline__ u64t ffma2(u64t a, u64t b, u64t c) {
    u64t d; asm("fma.rn.f32x2 %0, %1, %2, %3;" : "=l"(d) : "l"(a), "l"(b), "l"(c));
    return d;
}
__device__ __forceinline__ u64t splat2(float x) {
    u64t d; asm("mov.b64 %0, {%1, %1};" : "=l"(d) : "f"(x)); return d;
}
__device__ __forceinline__ float2 unpk(u64t a) {
    float2 r; asm("mov.b64 {%0, %1}, %2;" : "=f"(r.x), "=f"(r.y) : "l"(a)); return r;
}
__device__ __forceinline__ __half2 uint_as_h2(unsigned u) {
    union { unsigned u; __half2 h; } c; c.u = u; return c.h;
}
__device__ __forceinline__ unsigned h2_as_uint(__half2 h) {
    union { unsigned u; __half2 h; } c; c.h = h; return c.u;
}
__device__ __forceinline__ __half2 h2shflx(__half2 v, int m) {
    return uint_as_h2(__shfl_xor_sync(0xffffffffu, h2_as_uint(v), m));
}
__device__ __forceinline__ void mma16816(
    float& c0, float& c1, float& c2, float& c3,
    unsigned a0, unsigned a1, unsigned a2, unsigned a3,
    unsigned b0, unsigned b1)
{
    asm volatile(
        "mma.sync.aligned.m16n8k16.row.col.f32.f16.f16.f32 "
        "{%0,%1,%2,%3}, {%4,%5,%6,%7}, {%8,%9}, {%0,%1,%2,%3};"
        : "+f"(c0), "+f"(c1), "+f"(c2), "+f"(c3)
        : "r"(a0), "r"(a1), "r"(a2), "r"(a3), "r"(b0), "r"(b1));
}

// Scratch (~65 MB, L2-resident working set)
__device__ __half g_kv[NH * NPIX * 128];     // 8MB   [h][pix][lane16: k4|v4]
__device__ __half g_q[G_N * 3 * AD];         // 25MB  fp16 queries, PRESCALED by 1/8
__device__ int2   g_pts[NGH * KPTS];         // 6.3MB {pix<<4|fl, half2(wx1,wy1)}
__device__ __half g_attn[G_N * 3 * AD];      // 25MB  attention out fp16

__constant__ float c_fix[18] = {0,0,0, 1,0,0, 0,1,0, 0,0,1, -1,0,0, 0,-1,0};

// ---------------------------------------------------------------------------
// K1: kv maps via tensor cores.  Block = 64 pixels x 128 channels, K=256.
//   A (img^T) and B (Wk/Wv) converted to fp16 in smem; mma.m16n8k16 f32 accum.
//   Warp w: m-tile = w&3 (16 rows), n-half = w>>2 (64 channels).
// ---------------------------------------------------------------------------
__global__ __launch_bounds__(256) void kv_gemm(
    const float* __restrict__ img, const float* __restrict__ Wk,
    const float* __restrict__ Wv)
{
    const int m0 = blockIdx.x * 64;
    const int n0 = blockIdx.y * 128;
    __shared__ __half As[64][24];      // [m][k16]  pad 24 -> conflict-free
    __shared__ __half Bks[128][24];    // [n][k16]
    __shared__ __half Bvs[128][24];
    const int t    = threadIdx.x;
    const int w    = t >> 5;
    const int lane = t & 31;
    const int mt   = w & 3;            // m-tile within block (16 rows each)
    const int nh   = w >> 2;           // n-half (64 channels each)

    float acc[2][8][4];                // [map][n-tile][frag]
#pragma unroll
    for (int m2 = 0; m2 < 2; m2++)
#pragma unroll
        for (int j = 0; j < 8; j++)
#pragma unroll
            for (int f = 0; f < 4; f++) acc[m2][j][f] = 0.f;

    const int qrow = lane >> 2;        // 0..7
    const int qk   = (lane & 3) * 2;   // 0,2,4,6

    for (int c0 = 0; c0 < CIMG; c0 += 16) {
        // A: img[c0+k][m0+m] (16k x 64m fp32) -> As[m][k] fp16 (transpose)
        {
            int k = t >> 4, m4 = (t & 15) * 4;
            float4 v = *(const float4*)(img + (size_t)(c0 + k) * NPIX + m0 + m4);
            As[m4 + 0][k] = __float2half_rn(v.x);
            As[m4 + 1][k] = __float2half_rn(v.y);
            As[m4 + 2][k] = __float2half_rn(v.z);
            As[m4 + 3][k] = __float2half_rn(v.w);
        }
        // B: W[n0+n][c0+k] (128n x 16k fp32) -> Bs[n][k] fp16
#pragma unroll
        for (int rep = 0; rep < 2; rep++) {
            int idx = t + rep * 256;
            int n = idx >> 2, k4 = (idx & 3) * 4;
            float4 wk = *(const float4*)(Wk + (size_t)(n0 + n) * CIMG + c0 + k4);
            float4 wv = *(const float4*)(Wv + (size_t)(n0 + n) * CIMG + c0 + k4);
            union { uint2 u; __half2 h2[2]; } pk, pv;
            pk.h2[0] = __floats2half2_rn(wk.x, wk.y);
            pk.h2[1] = __floats2half2_rn(wk.z, wk.w);
            pv.h2[0] = __floats2half2_rn(wv.x, wv.y);
            pv.h2[1] = __floats2half2_rn(wv.z, wv.w);
            *(uint2*)&Bks[n][k4] = pk.u;
            *(uint2*)&Bvs[n][k4] = pv.u;
        }
        __syncthreads();

        // A fragment (row-major 16x16): two stacked m16k8 halves
        unsigned a0 = *(const unsigned*)&As[mt * 16 + qrow][qk];
        unsigned a1 = *(const unsigned*)&As[mt * 16 + qrow + 8][qk];
        unsigned a2 = *(const unsigned*)&As[mt * 16 + qrow][qk + 8];
        unsigned a3 = *(const unsigned*)&As[mt * 16 + qrow + 8][qk + 8];

#pragma unroll
        for (int j = 0; j < 8; j++) {
            int n = nh * 64 + j * 8 + qrow;      // B col for this lane
            unsigned bk0 = *(const unsigned*)&Bks[n][qk];
            unsigned bk1 = *(const unsigned*)&Bks[n][qk + 8];
            mma16816(acc[0][j][0], acc[0][j][1], acc[0][j][2], acc[0][j][3],
                     a0, a1, a2, a3, bk0, bk1);
            unsigned bv0 = *(const unsigned*)&Bvs[n][qk];
            unsigned bv1 = *(const unsigned*)&Bvs[n][qk + 8];
            mma16816(acc[1][j][0], acc[1][j][1], acc[1][j][2], acc[1][j][3],
                     a0, a1, a2, a3, bv0, bv1);
        }
        __syncthreads();
    }

    // Epilogue: C frag (r=lane>>2, cols 2c,2c+1; +8 rows for c2,c3) ->
    // g_kv interleaved layout: pixel*256B, k-group g: bytes g*16 (k) / +8 (v).
    const int colp = (lane & 3) * 2;
    const int p0 = m0 + mt * 16 + qrow;
#pragma unroll
    for (int j = 0; j < 8; j++) {
        int n_glob = n0 + nh * 64 + j * 8 + colp;
        int hh  = n_glob >> 6;
        int ch  = n_glob & 63;
        int off = (ch >> 2) * 8 + (ch & 3);      // within-pixel half offset (k)
#pragma unroll
        for (int m2 = 0; m2 < 2; m2++) {
            __half* base = g_kv + (size_t)(hh * NPIX) * 128 + off + (m2 ? 4 : 0);
            *(__half2*)(base + (size_t)p0 * 128) =
                __floats2half2_rn(acc[m2][j][0], acc[m2][j][1]);
            *(__half2*)(base + (size_t)(p0 + 8) * 128) =
                __floats2half2_rn(acc[m2][j][2], acc[m2][j][3]);
        }
    }
}

// ---------------------------------------------------------------------------
// K2: q = (features * 0.125) @ Wq -> fp16 g_q (unchanged)
// ---------------------------------------------------------------------------
__global__ __launch_bounds__(256) void q_gemm(
    const float* __restrict__ feat, const float* __restrict__ Wq)
{
    const int r0 = blockIdx.x * 64;
    const int n0 = blockIdx.y * 256;
    __shared__ float Fs[64][32];
    __shared__ float Ws[32][256];
    const int t = threadIdx.x;
#pragma unroll
    for (int rep = 0; rep < 8; rep++) {
        int idx = t + rep * 256;
        Fs[idx >> 5][idx & 31] =
            feat[(size_t)(r0 + (idx >> 5)) * GFDIM + (idx & 31)] * 0.125f;
    }
#pragma unroll
    for (int rep = 0; rep < 8; rep++) {
        int idx = t + rep * 256;
        int k = idx >> 6, n4 = (idx & 63) << 2;
        *(float4*)&Ws[k][n4] = *(const float4*)(Wq + (size_t)k * AD + n0 + n4);
    }
    __syncthreads();

    const int tc = t & 15, tr = t >> 4;
    u64t acc2[4][8];
#pragma unroll
    for (int i = 0; i < 4; i++)
#pragma unroll
        for (int j = 0; j < 8; j++) acc2[i][j] = 0ull;

#pragma unroll
    for (int k = 0; k < 32; k++) {
        u64t fs[4];
#pragma unroll
        for (int i = 0; i < 4; i++) fs[i] = splat2(Fs[tr * 4 + i][k]);
        u64t w[8];
#pragma unroll
        for (int q = 0; q < 4; q++) {
            ulonglong2 w2 = *(ulonglong2*)&Ws[k][q * 64 + tc * 4];
            w[q*2+0] = w2.x; w[q*2+1] = w2.y;
        }
#pragma unroll
        for (int i = 0; i < 4; i++)
#pragma unroll
            for (int j = 0; j < 8; j++) acc2[i][j] = ffma2(fs[i], w[j], acc2[i][j]);
    }
#pragma unroll
    for (int i = 0; i < 4; i++) {
        int r = r0 + tr * 4 + i;
#pragma unroll
        for (int q = 0; q < 4; q++) {
            float2 a = unpk(acc2[i][q*2+0]), b = unpk(acc2[i][q*2+1]);
            union { uint2 u; __half2 h2[2]; } cv;
            cv.h2[0] = __floats2half2_rn(a.x, a.y);
            cv.h2[1] = __floats2half2_rn(b.x, b.y);
            *(uint2*)&g_q[(size_t)r * AD + n0 + q * 64 + tc * 4] = cv.u;
        }
    }
}

// ---------------------------------------------------------------------------
// K3: sigpp (unchanged; qmean factor 8/3 undoes the 1/8 q prescale)
// ---------------------------------------------------------------------------
__global__ __launch_bounds__(256) void sigpp(
    const float* __restrict__ means, const float* __restrict__ scales,
    const float* __restrict__ rots, const float* __restrict__ transforms,
    const float* __restrict__ proj, const float* __restrict__ W_off,
    const float* __restrict__ b_off)
{
    const int r0 = blockIdx.x * 64;
    __shared__ float Xs[64][69];
    __shared__ float Ws[67][20];
    __shared__ float bs[20];
    __shared__ float sh_learn[64][18];
    __shared__ float sh_rot[8][9];
    __shared__ float sh_scl[8][3];
    __shared__ float sh_proj[12];
    const int t = threadIdx.x;

    for (int idx = t; idx < 64 * 64; idx += 256) {
        int rl = idx >> 6, c = idx & 63;
        int r = r0 + rl, g = r >> 3, h = r & 7;
        const __half* q = g_q + (size_t)(g * 3) * AD + h * HDIM + c;
        Xs[rl][3 + c] = (__half2float(q[0]) + __half2float(q[AD])
                       + __half2float(q[2 * AD])) * (8.f / 3.f);
    }
    if (t < 64) {
        int r = r0 + t, g = r >> 3;
        float mx = means[g*3], my = means[g*3+1], mz = means[g*3+2];
        const float* T = transforms + (size_t)g * 16;
        Xs[t][0] = T[0]*mx + T[1]*my + T[2] *mz + T[3];
        Xs[t][1] = T[4]*mx + T[5]*my + T[6] *mz + T[7];
        Xs[t][2] = T[8]*mx + T[9]*my + T[10]*mz + T[11];
    }
    for (int idx = t; idx < 67 * 20; idx += 256) {
        int i = idx / 20, o = idx % 20;
        Ws[i][o] = (o < 18) ? W_off[i * 18 + o] : 0.f;
    }
    if (t < 20) bs[t] = (t < 18) ? b_off[t] : 0.f;
    if (t < 12) sh_proj[t] = proj[t];
    if (t >= 32 && t < 40) {
        int gl = t - 32, g = (r0 >> 3) + gl;
        float qw = rots[g*4+0], qx = rots[g*4+1], qy = rots[g*4+2], qz = rots[g*4+3];
        float qn = rsqrtf(qw*qw + qx*qx + qy*qy + qz*qz);
        qw *= qn; qx *= qn; qy *= qn; qz *= qn;
        sh_rot[gl][0] = 1.f-2.f*(qy*qy+qz*qz); sh_rot[gl][1] = 2.f*(qx*qy-qw*qz);
        sh_rot[gl][2] = 2.f*(qx*qz+qw*qy);     sh_rot[gl][3] = 2.f*(qx*qy+qw*qz);
        sh_rot[gl][4] = 1.f-2.f*(qx*qx+qz*qz); sh_rot[gl][5] = 2.f*(qy*qz-qw*qx);
        sh_rot[gl][6] = 2.f*(qx*qz-qw*qy);     sh_rot[gl][7] = 2.f*(qy*qz+qw*qx);
        sh_rot[gl][8] = 1.f-2.f*(qx*qx+qy*qy);
        sh_scl[gl][0] = scales[g*3+0];
        sh_scl[gl][1] = scales[g*3+1];
        sh_scl[gl][2] = scales[g*3+2];
    }
    __syncthreads();

    {
        const int rl = t & 63, og = t >> 6;
        const int obase = og * 5;
        float acc[5] = {0.f, 0.f, 0.f, 0.f, 0.f};
        for (int i = 0; i < 67; i++) {
            float x = Xs[rl][i];
#pragma unroll
            for (int u = 0; u < 5; u++) acc[u] += x * Ws[i][obase + u];
        }
        const int on = (og == 3) ? 3 : 5;
        for (int u = 0; u < on; u++) {
            float z = acc[u] + bs[obase + u];
            z = fminf(fmaxf(z, -SIGC), SIGC);
            sh_learn[rl][obase + u] = 1.f / (1.f + __expf(-z)) - 0.5f;
        }
    }
    __syncthreads();

#pragma unroll
    for (int it = 0; it < 3; it++) {
        int id = t + it * 256;
        int rl = id / KPTS, kp = id - rl * KPTS;
        int gl = rl >> 3;
        float s0, s1, s2;
        if (kp < 6) { s0 = c_fix[kp*3+0]; s1 = c_fix[kp*3+1]; s2 = c_fix[kp*3+2]; }
        else { const float* lp = &sh_learn[rl][(kp - 6) * 3];
               s0 = lp[0]; s1 = lp[1]; s2 = lp[2]; }
        float v0 = s0 * sh_scl[gl][0], v1 = s1 * sh_scl[gl][1], v2 = s2 * sh_scl[gl][2];
        const float* R = sh_rot[gl];
        float px = R[0]*v0 + R[3]*v1 + R[6]*v2 + Xs[rl][0];
        float py = R[1]*v0 + R[4]*v1 + R[7]*v2 + Xs[rl][1];
        float pz = R[2]*v0 + R[5]*v1 + R[8]*v2 + Xs[rl][2];
        float p0 = sh_proj[0]*px + sh_proj[1]*py + sh_proj[2] *pz + sh_proj[3];
        float p1 = sh_proj[4]*px + sh_proj[5]*py + sh_proj[6] *pz + sh_proj[7];
        float p2 = sh_proj[8]*px + sh_proj[9]*py + sh_proj[10]*pz + sh_proj[11];
        float zz = fmaxf(p2, 1e-5f);
        float u = p0 / zz, v = p1 / zz;
        const float lim = 0.9999f * (float)IMG;
        float xf = fminf(fmaxf(u, 0.f), lim) - 0.5f;
        float yf = fminf(fmaxf(v, 0.f), lim) - 0.5f;
        float fx0 = floorf(xf), fy0 = floorf(yf);
        float wx1 = xf - fx0, wy1 = yf - fy0;
        int x0 = (int)fx0, y0 = (int)fy0;
        int pix = y0 * IMG + x0;
        int vx0 = (unsigned)x0       < IMG;
        int vx1 = (unsigned)(x0 + 1) < IMG;
        int vy0 = (unsigned)y0       < IMG;
        int vy1 = (unsigned)(y0 + 1) < IMG;
        int fl = (vy0 & vx0) | ((vy0 & vx1) << 1) | ((vy1 & vx0) << 2) | ((vy1 & vx1) << 3);
        union { __half2 h; int i; } wv;
        wv.h = __floats2half2_rn(wx1, wy1);
        g_pts[(size_t)(r0 + rl) * KPTS + kp] = make_int2((pix << 4) | fl, wv.i);
    }
}

// ---------------------------------------------------------------------------
// K4: gather_attn (unchanged from R13 — half2 datapath, prefetch pipeline)
// ---------------------------------------------------------------------------
__global__ __launch_bounds__(256) void gather_attn()
{
    const int g    = blockIdx.x;
    const int tid  = threadIdx.x;
    const int h    = tid >> 5;
    const int lane = tid & 31;
    const int l    = lane & 15;
    const int half = lane >> 4;

    const __half* qr = g_q + (size_t)(g * 3) * AD + h * HDIM + l * 4;
    uint2 q0u = *(const uint2*)(qr);
    uint2 q1u = *(const uint2*)(qr + AD);
    uint2 q2u = *(const uint2*)(qr + 2 * AD);
    __half2 Q0a = uint_as_h2(q0u.x), Q0b = uint_as_h2(q0u.y);
    __half2 Q1a = uint_as_h2(q1u.x), Q1b = uint_as_h2(q1u.y);
    __half2 Q2a = uint_as_h2(q2u.x), Q2b = uint_as_h2(q2u.y);

    int2 pt;
    { int kpl = lane < KPTS ? lane : KPTS - 1;
      pt = g_pts[(size_t)(g * NH + h) * KPTS + kpl]; }

    const char* kvb = (const char*)g_kv + (size_t)h * NPIX * 256 + l * 16;

    float s0v = 0.f, s1v = 0.f, s2v = 0.f;
    const __half2 hz = __float2half2_rn(0.f);
    __half2 o0a = hz, o0b = hz, o1a = hz, o1b = hz, o2a = hz, o2b = hz;

    uint4 T0, T1, T2, T3;
    float cwx1, cwy1;
    {
        int w0 = __shfl_sync(0xffffffffu, pt.x, half);
        int w1 = __shfl_sync(0xffffffffu, pt.y, half);
        int bf = w0 & 15;
        float2 w = __half22float2(uint_as_h2((unsigned)w1));
        cwx1 = w.x; cwy1 = w.y;
        const char* p = kvb + ((long)(w0 >> 4) << 8);
        T0 = T1 = T2 = T3 = make_uint4(0, 0, 0, 0);
        if (bf & 1) T0 = *(const uint4*)(p);
        if (bf & 2) T1 = *(const uint4*)(p + 256);
        if (bf & 4) T2 = *(const uint4*)(p + IMG * 256);
        if (bf & 8) T3 = *(const uint4*)(p + IMG * 256 + 256);
    }

#pragma unroll
    for (int i = 0; i < KPTS / 2; i++) {
        uint4 N0, N1, N2, N3;
        float nwx1 = 0.f, nwy1 = 0.f;
        N0 = N1 = N2 = N3 = make_uint4(0, 0, 0, 0);
        if (i < KPTS / 2 - 1) {
            int src = 2 * (i + 1) + half;
            int w0 = __shfl_sync(0xffffffffu, pt.x, src);
            int w1 = __shfl_sync(0xffffffffu, pt.y, src);
            int bf = w0 & 15;
            float2 w = __half22float2(uint_as_h2((unsigned)w1));
            nwx1 = w.x; nwy1 = w.y;
            const char* p = kvb + ((long)(w0 >> 4) << 8);
            if (bf & 1) N0 = *(const uint4*)(p);
            if (bf & 2) N1 = *(const uint4*)(p + 256);
            if (bf & 4) N2 = *(const uint4*)(p + IMG * 256);
            if (bf & 8) N3 = *(const uint4*)(p + IMG * 256 + 256);
        }

        float wx0 = 1.f - cwx1, wy0 = 1.f - cwy1;
        __half2 hw00 = __float2half2_rn(wx0  * wy0);
        __half2 hw01 = __float2half2_rn(cwx1 * wy0);
        __half2 hw10 = __float2half2_rn(wx0  * cwy1);
        __half2 hw11 = __float2half2_rn(cwx1 * cwy1);
        union { uint4 u; __half2 h2[4]; } A, B, C, D;
        A.u = T0; B.u = T1; C.u = T2; D.u = T3;
        __half2 hk0 = __hfma2(hw00, A.h2[0], __hfma2(hw01, B.h2[0],
                      __hfma2(hw10, C.h2[0], __hmul2(hw11, D.h2[0]))));
        __half2 hk1 = __hfma2(hw00, A.h2[1], __hfma2(hw01, B.h2[1],
                      __hfma2(hw10, C.h2[1], __hmul2(hw11, D.h2[1]))));
        __half2 hv0 = __hfma2(hw00, A.h2[2], __hfma2(hw01, B.h2[2],
                      __hfma2(hw10, C.h2[2], __hmul2(hw11, D.h2[2]))));
        __half2 hv1 = __hfma2(hw00, A.h2[3], __hfma2(hw01, B.h2[3],
                      __hfma2(hw10, C.h2[3], __hmul2(hw11, D.h2[3]))));

        __half2 d0h = __hfma2(Q0a, hk0, __hmul2(Q0b, hk1));
        __half2 d1h = __hfma2(Q1a, hk0, __hmul2(Q1b, hk1));
        __half2 d2h = __hfma2(Q2a, hk0, __hmul2(Q2b, hk1));
#pragma unroll
        for (int off = 8; off > 0; off >>= 1) {
            d0h = __hadd2(d0h, h2shflx(d0h, off));
            d1h = __hadd2(d1h, h2shflx(d1h, off));
            d2h = __hadd2(d2h, h2shflx(d2h, off));
        }
        float2 f0 = __half22float2(d0h);
        float2 f1 = __half22float2(d1h);
        float2 f2 = __half22float2(d2h);
        float e0 = __expf(f0.x + f0.y);
        float e1 = __expf(f1.x + f1.y);
        float e2 = __expf(f2.x + f2.y);
        s0v += e0; s1v += e1; s2v += e2;
        __half2 e0h = __float2half2_rn(e0);
        __half2 e1h = __float2half2_rn(e1);
        __half2 e2h = __float2half2_rn(e2);
        o0a = __hfma2(e0h, hv0, o0a); o0b = __hfma2(e0h, hv1, o0b);
        o1a = __hfma2(e1h, hv0, o1a); o1b = __hfma2(e1h, hv1, o1b);
        o2a = __hfma2(e2h, hv0, o2a); o2b = __hfma2(e2h, hv1, o2b);

        T0 = N0; T1 = N1; T2 = N2; T3 = N3;
        cwx1 = nwx1; cwy1 = nwy1;
    }

    o0a = __hadd2(o0a, h2shflx(o0a, 16)); o0b = __hadd2(o0b, h2shflx(o0b, 16));
    o1a = __hadd2(o1a, h2shflx(o1a, 16)); o1b = __hadd2(o1b, h2shflx(o1b, 16));
    o2a = __hadd2(o2a, h2shflx(o2a, 16)); o2b = __hadd2(o2b, h2shflx(o2b, 16));
    s0v += __shfl_xor_sync(0xffffffffu, s0v, 16);
    s1v += __shfl_xor_sync(0xffffffffu, s1v, 16);
    s2v += __shfl_xor_sync(0xffffffffu, s2v, 16);

    if (half == 0) {
        __half* orow = g_attn + (size_t)(g * 3) * AD + h * HDIM + l * 4;
        __half2 i0 = __float2half2_rn(1.f / s0v);
        __half2 i1 = __float2half2_rn(1.f / s1v);
        __half2 i2 = __float2half2_rn(1.f / s2v);
        uint2 st;
        st.x = h2_as_uint(__hmul2(o0a, i0)); st.y = h2_as_uint(__hmul2(o0b, i0));
        *(uint2*)(orow) = st;
        st.x = h2_as_uint(__hmul2(o1a, i1)); st.y = h2_as_uint(__hmul2(o1b, i1));
        *(uint2*)(orow + AD) = st;
        st.x = h2_as_uint(__hmul2(o2a, i2)); st.y = h2_as_uint(__hmul2(o2b, i2));
        *(uint2*)(orow + 2 * AD) = st;
    }
}

// ---------------------------------------------------------------------------
// K5: out_gemm (unchanged)
// ---------------------------------------------------------------------------
__global__ __launch_bounds__(256) void out_gemm(
    const float* __restrict__ Wout, const float* __restrict__ b_out,
    const float* __restrict__ feat, float* __restrict__ out)
{
    const int r0 = blockIdx.x * 64;
    __shared__ float Xs[32][66];
    __shared__ float Ws[32][32];
    const int t = threadIdx.x;
    const int c = t & 31, rb = (t >> 5) * 8;
    u64t acc2[4] = {0ull, 0ull, 0ull, 0ull};

    for (int k0 = 0; k0 < AD; k0 += 32) {
#pragma unroll
        for (int rep = 0; rep < 8; rep++) {
            int idx = t + rep * 256;
            int row = idx >> 5, kc = idx & 31;
            Xs[kc][row] = __half2float(
                g_attn[(size_t)(r0 + row) * AD + k0 + kc]);
        }
#pragma unroll
        for (int rep = 0; rep < 4; rep++) {
            int idx = t + rep * 256;
            Ws[idx >> 5][idx & 31] = Wout[(size_t)(k0 + (idx >> 5)) * GFDIM + (idx & 31)];
        }
        __syncthreads();
#pragma unroll
        for (int kk = 0; kk < 32; kk++) {
            u64t w = splat2(Ws[kk][c]);
#pragma unroll
            for (int i = 0; i < 4; i++)
                acc2[i] = ffma2(w, *(const u64t*)&Xs[kk][rb + 2 * i], acc2[i]);
        }
        __syncthreads();
    }
    float b = b_out[c];
#pragma unroll
    for (int i = 0; i < 4; i++) {
        float2 r = unpk(acc2[i]);
        int row0 = r0 + rb + 2 * i;
        out[(size_t)row0 * GFDIM + c]       = r.x + b + feat[(size_t)row0 * GFDIM + c];
        out[(size_t)(row0 + 1) * GFDIM + c] = r.y + b + feat[(size_t)(row0 + 1) * GFDIM + c];
    }
}

// ---------------------------------------------------------------------------
extern "C" void kernel_launch(void* const* d_in, const int* in_sizes, int n_in,
                              void* d_out, int out_size)
{
    const float* means      = (const float*)d_in[0];
    const float* scales     = (const float*)d_in[1];
    const float* rotations  = (const float*)d_in[2];
    const float* features   = (const float*)d_in[3];
    const float* transforms = (const float*)d_in[4];
    const float* projection = (const float*)d_in[5];
    const float* image_feat = (const float*)d_in[6];
    const float* Wq         = (const float*)d_in[7];
    const float* Wk         = (const float*)d_in[8];
    const float* Wv         = (const float*)d_in[9];
    const float* W_off      = (const float*)d_in[10];
    const float* b_off      = (const float*)d_in[11];
    const float* Wout       = (const float*)d_in[12];
    const float* b_out      = (const float*)d_in[13];
    float* out = (float*)d_out;

    kv_gemm<<<dim3(NPIX / 64, AD / 128), 256>>>(image_feat, Wk, Wv);
    q_gemm<<<dim3(G_N * 3 / 64, AD / 256), 256>>>(features, Wq);
    sigpp<<<NGH / 64, 256>>>(means, scales, rotations, transforms,
                             projection, W_off, b_off);
    gather_attn<<<G_N, 256>>>();
    out_gemm<<<G_N * 3 / 64, 256>>>(Wout, b_out, features, out);
}

// round 15
// speedup vs baseline: 1.3587x; 1.1066x over previous
#include <cuda_runtime.h>
#include <cuda_fp16.h>

#define G_N   8192
#define NH    8
#define HDIM  64
#define AD    512
#define GFDIM 32
#define CIMG  256
#define IMG   64
#define NPIX  (IMG*IMG)
#define KPTS  12
#define SIGC  9.21f
#define NGH   (G_N * NH)

typedef unsigned long long u64t;

__device__ __forceinline__ __half2 uint_as_h2(unsigned u) {
    union { unsigned u; __half2 h; } c; c.u = u; return c.h;
}
__device__ __forceinline__ unsigned h2_as_uint(__half2 h) {
    union { unsigned u; __half2 h; } c; c.h = h; return c.u;
}
__device__ __forceinline__ __half2 h2shflx(__half2 v, int m) {
    return uint_as_h2(__shfl_xor_sync(0xffffffffu, h2_as_uint(v), m));
}
__device__ __forceinline__ void mma16816(
    float& c0, float& c1, float& c2, float& c3,
    unsigned a0, unsigned a1, unsigned a2, unsigned a3,
    unsigned b0, unsigned b1)
{
    asm volatile(
        "mma.sync.aligned.m16n8k16.row.col.f32.f16.f16.f32 "
        "{%0,%1,%2,%3}, {%4,%5,%6,%7}, {%8,%9}, {%0,%1,%2,%3};"
        : "+f"(c0), "+f"(c1), "+f"(c2), "+f"(c3)
        : "r"(a0), "r"(a1), "r"(a2), "r"(a3), "r"(b0), "r"(b1));
}

// Scratch (~65 MB, L2-resident working set)
__device__ __half g_kv[NH * NPIX * 128];     // 8MB   [h][pix][lane16: k4|v4]
__device__ __half g_q[G_N * 3 * AD];         // 25MB  fp16 queries, PRESCALED by 1/8
__device__ int2   g_pts[NGH * KPTS];         // 6.3MB {pix<<4|fl, half2(wx1,wy1)}
__device__ __half g_attn[G_N * 3 * AD];      // 25MB  attention out fp16

__constant__ float c_fix[18] = {0,0,0, 1,0,0, 0,1,0, 0,0,1, -1,0,0, 0,-1,0};

// ---------------------------------------------------------------------------
// K1: kv maps via tensor cores (unchanged from R14)
// ---------------------------------------------------------------------------
__global__ __launch_bounds__(256) void kv_gemm(
    const float* __restrict__ img, const float* __restrict__ Wk,
    const float* __restrict__ Wv)
{
    const int m0 = blockIdx.x * 64;
    const int n0 = blockIdx.y * 128;
    __shared__ __half As[64][24];
    __shared__ __half Bks[128][24];
    __shared__ __half Bvs[128][24];
    const int t    = threadIdx.x;
    const int w    = t >> 5;
    const int lane = t & 31;
    const int mt   = w & 3;
    const int nh   = w >> 2;

    float acc[2][8][4];
#pragma unroll
    for (int m2 = 0; m2 < 2; m2++)
#pragma unroll
        for (int j = 0; j < 8; j++)
#pragma unroll
            for (int f = 0; f < 4; f++) acc[m2][j][f] = 0.f;

    const int qrow = lane >> 2;
    const int qk   = (lane & 3) * 2;

    for (int c0 = 0; c0 < CIMG; c0 += 16) {
        {
            int k = t >> 4, m4 = (t & 15) * 4;
            float4 v = *(const float4*)(img + (size_t)(c0 + k) * NPIX + m0 + m4);
            As[m4 + 0][k] = __float2half_rn(v.x);
            As[m4 + 1][k] = __float2half_rn(v.y);
            As[m4 + 2][k] = __float2half_rn(v.z);
            As[m4 + 3][k] = __float2half_rn(v.w);
        }
#pragma unroll
        for (int rep = 0; rep < 2; rep++) {
            int idx = t + rep * 256;
            int n = idx >> 2, k4 = (idx & 3) * 4;
            float4 wk = *(const float4*)(Wk + (size_t)(n0 + n) * CIMG + c0 + k4);
            float4 wv = *(const float4*)(Wv + (size_t)(n0 + n) * CIMG + c0 + k4);
            union { uint2 u; __half2 h2[2]; } pk, pv;
            pk.h2[0] = __floats2half2_rn(wk.x, wk.y);
            pk.h2[1] = __floats2half2_rn(wk.z, wk.w);
            pv.h2[0] = __floats2half2_rn(wv.x, wv.y);
            pv.h2[1] = __floats2half2_rn(wv.z, wv.w);
            *(uint2*)&Bks[n][k4] = pk.u;
            *(uint2*)&Bvs[n][k4] = pv.u;
        }
        __syncthreads();

        unsigned a0 = *(const unsigned*)&As[mt * 16 + qrow][qk];
        unsigned a1 = *(const unsigned*)&As[mt * 16 + qrow + 8][qk];
        unsigned a2 = *(const unsigned*)&As[mt * 16 + qrow][qk + 8];
        unsigned a3 = *(const unsigned*)&As[mt * 16 + qrow + 8][qk + 8];

#pragma unroll
        for (int j = 0; j < 8; j++) {
            int n = nh * 64 + j * 8 + qrow;
            unsigned bk0 = *(const unsigned*)&Bks[n][qk];
            unsigned bk1 = *(const unsigned*)&Bks[n][qk + 8];
            mma16816(acc[0][j][0], acc[0][j][1], acc[0][j][2], acc[0][j][3],
                     a0, a1, a2, a3, bk0, bk1);
            unsigned bv0 = *(const unsigned*)&Bvs[n][qk];
            unsigned bv1 = *(const unsigned*)&Bvs[n][qk + 8];
            mma16816(acc[1][j][0], acc[1][j][1], acc[1][j][2], acc[1][j][3],
                     a0, a1, a2, a3, bv0, bv1);
        }
        __syncthreads();
    }

    const int colp = (lane & 3) * 2;
    const int p0 = m0 + mt * 16 + qrow;
#pragma unroll
    for (int j = 0; j < 8; j++) {
        int n_glob = n0 + nh * 64 + j * 8 + colp;
        int hh  = n_glob >> 6;
        int ch  = n_glob & 63;
        int off = (ch >> 2) * 8 + (ch & 3);
#pragma unroll
        for (int m2 = 0; m2 < 2; m2++) {
            __half* base = g_kv + (size_t)(hh * NPIX) * 128 + off + (m2 ? 4 : 0);
            *(__half2*)(base + (size_t)p0 * 128) =
                __floats2half2_rn(acc[m2][j][0], acc[m2][j][1]);
            *(__half2*)(base + (size_t)(p0 + 8) * 128) =
                __floats2half2_rn(acc[m2][j][2], acc[m2][j][3]);
        }
    }
}

// ---------------------------------------------------------------------------
// K2: q = (features * 0.125) @ Wq via tensor cores -> fp16 g_q.
//   Block = 32 rows x 512 cols, 8 warps (mt 0..1, nh 0..3), K=32.
// ---------------------------------------------------------------------------
__global__ __launch_bounds__(256) void q_gemm(
    const float* __restrict__ feat, const float* __restrict__ Wq)
{
    const int r0 = blockIdx.x * 32;
    __shared__ __half As[32][36];      // pad 36 -> bank stride 18, conflict-free
    __shared__ __half Bs[AD][36];      // [n][k]
    const int t    = threadIdx.x;
    const int w    = t >> 5;
    const int lane = t & 31;
    const int mt   = w & 1;
    const int nh   = w >> 1;
    const int qrow = lane >> 2;
    const int qk   = (lane & 3) * 2;

    // A: feat[r0..r0+31][0..31] * 0.125 -> fp16
    {
        int r = t >> 3, k4 = (t & 7) * 4;
        float4 v = *(const float4*)(feat + (size_t)(r0 + r) * GFDIM + k4);
        As[r][k4 + 0] = __float2half_rn(v.x * 0.125f);
        As[r][k4 + 1] = __float2half_rn(v.y * 0.125f);
        As[r][k4 + 2] = __float2half_rn(v.z * 0.125f);
        As[r][k4 + 3] = __float2half_rn(v.w * 0.125f);
    }
    // B: Wq[k][n] -> Bs[n][k] fp16 (transpose-on-store)
#pragma unroll
    for (int rep = 0; rep < 16; rep++) {
        int idx = t + rep * 256;
        int k = idx >> 7, n4 = (idx & 127) * 4;
        float4 v = *(const float4*)(Wq + (size_t)k * AD + n4);
        Bs[n4 + 0][k] = __float2half_rn(v.x);
        Bs[n4 + 1][k] = __float2half_rn(v.y);
        Bs[n4 + 2][k] = __float2half_rn(v.z);
        Bs[n4 + 3][k] = __float2half_rn(v.w);
    }
    __syncthreads();

    float acc[16][4];
#pragma unroll
    for (int j = 0; j < 16; j++)
#pragma unroll
        for (int f = 0; f < 4; f++) acc[j][f] = 0.f;

#pragma unroll
    for (int ks = 0; ks < 2; ks++) {
        int k0 = ks * 16;
        unsigned a0 = *(const unsigned*)&As[mt * 16 + qrow][k0 + qk];
        unsigned a1 = *(const unsigned*)&As[mt * 16 + qrow + 8][k0 + qk];
        unsigned a2 = *(const unsigned*)&As[mt * 16 + qrow][k0 + qk + 8];
        unsigned a3 = *(const unsigned*)&As[mt * 16 + qrow + 8][k0 + qk + 8];
#pragma unroll
        for (int j = 0; j < 16; j++) {
            int n = nh * 128 + j * 8 + qrow;
            unsigned b0 = *(const unsigned*)&Bs[n][k0 + qk];
            unsigned b1 = *(const unsigned*)&Bs[n][k0 + qk + 8];
            mma16816(acc[j][0], acc[j][1], acc[j][2], acc[j][3],
                     a0, a1, a2, a3, b0, b1);
        }
    }

    const int colp = (lane & 3) * 2;
    const int r = r0 + mt * 16 + qrow;
#pragma unroll
    for (int j = 0; j < 16; j++) {
        int col = nh * 128 + j * 8 + colp;
        *(__half2*)&g_q[(size_t)r * AD + col] =
            __floats2half2_rn(acc[j][0], acc[j][1]);
        *(__half2*)&g_q[(size_t)(r + 8) * AD + col] =
            __floats2half2_rn(acc[j][2], acc[j][3]);
    }
}

// ---------------------------------------------------------------------------
// K3: sigpp (unchanged; qmean factor 8/3 undoes the 1/8 q prescale)
// ---------------------------------------------------------------------------
__global__ __launch_bounds__(256) void sigpp(
    const float* __restrict__ means, const float* __restrict__ scales,
    const float* __restrict__ rots, const float* __restrict__ transforms,
    const float* __restrict__ proj, const float* __restrict__ W_off,
    const float* __restrict__ b_off)
{
    const int r0 = blockIdx.x * 64;
    __shared__ float Xs[64][69];
    __shared__ float Ws[67][20];
    __shared__ float bs[20];
    __shared__ float sh_learn[64][18];
    __shared__ float sh_rot[8][9];
    __shared__ float sh_scl[8][3];
    __shared__ float sh_proj[12];
    const int t = threadIdx.x;

    for (int idx = t; idx < 64 * 64; idx += 256) {
        int rl = idx >> 6, c = idx & 63;
        int r = r0 + rl, g = r >> 3, h = r & 7;
        const __half* q = g_q + (size_t)(g * 3) * AD + h * HDIM + c;
        Xs[rl][3 + c] = (__half2float(q[0]) + __half2float(q[AD])
                       + __half2float(q[2 * AD])) * (8.f / 3.f);
    }
    if (t < 64) {
        int r = r0 + t, g = r >> 3;
        float mx = means[g*3], my = means[g*3+1], mz = means[g*3+2];
        const float* T = transforms + (size_t)g * 16;
        Xs[t][0] = T[0]*mx + T[1]*my + T[2] *mz + T[3];
        Xs[t][1] = T[4]*mx + T[5]*my + T[6] *mz + T[7];
        Xs[t][2] = T[8]*mx + T[9]*my + T[10]*mz + T[11];
    }
    for (int idx = t; idx < 67 * 20; idx += 256) {
        int i = idx / 20, o = idx % 20;
        Ws[i][o] = (o < 18) ? W_off[i * 18 + o] : 0.f;
    }
    if (t < 20) bs[t] = (t < 18) ? b_off[t] : 0.f;
    if (t < 12) sh_proj[t] = proj[t];
    if (t >= 32 && t < 40) {
        int gl = t - 32, g = (r0 >> 3) + gl;
        float qw = rots[g*4+0], qx = rots[g*4+1], qy = rots[g*4+2], qz = rots[g*4+3];
        float qn = rsqrtf(qw*qw + qx*qx + qy*qy + qz*qz);
        qw *= qn; qx *= qn; qy *= qn; qz *= qn;
        sh_rot[gl][0] = 1.f-2.f*(qy*qy+qz*qz); sh_rot[gl][1] = 2.f*(qx*qy-qw*qz);
        sh_rot[gl][2] = 2.f*(qx*qz+qw*qy);     sh_rot[gl][3] = 2.f*(qx*qy+qw*qz);
        sh_rot[gl][4] = 1.f-2.f*(qx*qx+qz*qz); sh_rot[gl][5] = 2.f*(qy*qz-qw*qx);
        sh_rot[gl][6] = 2.f*(qx*qz-qw*qy);     sh_rot[gl][7] = 2.f*(qy*qz+qw*qx);
        sh_rot[gl][8] = 1.f-2.f*(qx*qx+qy*qy);
        sh_scl[gl][0] = scales[g*3+0];
        sh_scl[gl][1] = scales[g*3+1];
        sh_scl[gl][2] = scales[g*3+2];
    }
    __syncthreads();

    {
        const int rl = t & 63, og = t >> 6;
        const int obase = og * 5;
        float acc[5] = {0.f, 0.f, 0.f, 0.f, 0.f};
        for (int i = 0; i < 67; i++) {
            float x = Xs[rl][i];
#pragma unroll
            for (int u = 0; u < 5; u++) acc[u] += x * Ws[i][obase + u];
        }
        const int on = (og == 3) ? 3 : 5;
        for (int u = 0; u < on; u++) {
            float z = acc[u] + bs[obase + u];
            z = fminf(fmaxf(z, -SIGC), SIGC);
            sh_learn[rl][obase + u] = 1.f / (1.f + __expf(-z)) - 0.5f;
        }
    }
    __syncthreads();

#pragma unroll
    for (int it = 0; it < 3; it++) {
        int id = t + it * 256;
        int rl = id / KPTS, kp = id - rl * KPTS;
        int gl = rl >> 3;
        float s0, s1, s2;
        if (kp < 6) { s0 = c_fix[kp*3+0]; s1 = c_fix[kp*3+1]; s2 = c_fix[kp*3+2]; }
        else { const float* lp = &sh_learn[rl][(kp - 6) * 3];
               s0 = lp[0]; s1 = lp[1]; s2 = lp[2]; }
        float v0 = s0 * sh_scl[gl][0], v1 = s1 * sh_scl[gl][1], v2 = s2 * sh_scl[gl][2];
        const float* R = sh_rot[gl];
        float px = R[0]*v0 + R[3]*v1 + R[6]*v2 + Xs[rl][0];
        float py = R[1]*v0 + R[4]*v1 + R[7]*v2 + Xs[rl][1];
        float pz = R[2]*v0 + R[5]*v1 + R[8]*v2 + Xs[rl][2];
        float p0 = sh_proj[0]*px + sh_proj[1]*py + sh_proj[2] *pz + sh_proj[3];
        float p1 = sh_proj[4]*px + sh_proj[5]*py + sh_proj[6] *pz + sh_proj[7];
        float p2 = sh_proj[8]*px + sh_proj[9]*py + sh_proj[10]*pz + sh_proj[11];
        float zz = fmaxf(p2, 1e-5f);
        float u = p0 / zz, v = p1 / zz;
        const float lim = 0.9999f * (float)IMG;
        float xf = fminf(fmaxf(u, 0.f), lim) - 0.5f;
        float yf = fminf(fmaxf(v, 0.f), lim) - 0.5f;
        float fx0 = floorf(xf), fy0 = floorf(yf);
        float wx1 = xf - fx0, wy1 = yf - fy0;
        int x0 = (int)fx0, y0 = (int)fy0;
        int pix = y0 * IMG + x0;
        int vx0 = (unsigned)x0       < IMG;
        int vx1 = (unsigned)(x0 + 1) < IMG;
        int vy0 = (unsigned)y0       < IMG;
        int vy1 = (unsigned)(y0 + 1) < IMG;
        int fl = (vy0 & vx0) | ((vy0 & vx1) << 1) | ((vy1 & vx0) << 2) | ((vy1 & vx1) << 3);
        union { __half2 h; int i; } wv;
        wv.h = __floats2half2_rn(wx1, wy1);
        g_pts[(size_t)(r0 + rl) * KPTS + kp] = make_int2((pix << 4) | fl, wv.i);
    }
}

// ---------------------------------------------------------------------------
// K4: gather_attn (unchanged from R13/R14)
// ---------------------------------------------------------------------------
__global__ __launch_bounds__(256) void gather_attn()
{
    const int g    = blockIdx.x;
    const int tid  = threadIdx.x;
    const int h    = tid >> 5;
    const int lane = tid & 31;
    const int l    = lane & 15;
    const int half = lane >> 4;

    const __half* qr = g_q + (size_t)(g * 3) * AD + h * HDIM + l * 4;
    uint2 q0u = *(const uint2*)(qr);
    uint2 q1u = *(const uint2*)(qr + AD);
    uint2 q2u = *(const uint2*)(qr + 2 * AD);
    __half2 Q0a = uint_as_h2(q0u.x), Q0b = uint_as_h2(q0u.y);
    __half2 Q1a = uint_as_h2(q1u.x), Q1b = uint_as_h2(q1u.y);
    __half2 Q2a = uint_as_h2(q2u.x), Q2b = uint_as_h2(q2u.y);

    int2 pt;
    { int kpl = lane < KPTS ? lane : KPTS - 1;
      pt = g_pts[(size_t)(g * NH + h) * KPTS + kpl]; }

    const char* kvb = (const char*)g_kv + (size_t)h * NPIX * 256 + l * 16;

    float s0v = 0.f, s1v = 0.f, s2v = 0.f;
    const __half2 hz = __float2half2_rn(0.f);
    __half2 o0a = hz, o0b = hz, o1a = hz, o1b = hz, o2a = hz, o2b = hz;

    uint4 T0, T1, T2, T3;
    float cwx1, cwy1;
    {
        int w0 = __shfl_sync(0xffffffffu, pt.x, half);
        int w1 = __shfl_sync(0xffffffffu, pt.y, half);
        int bf = w0 & 15;
        float2 w = __half22float2(uint_as_h2((unsigned)w1));
        cwx1 = w.x; cwy1 = w.y;
        const char* p = kvb + ((long)(w0 >> 4) << 8);
        T0 = T1 = T2 = T3 = make_uint4(0, 0, 0, 0);
        if (bf & 1) T0 = *(const uint4*)(p);
        if (bf & 2) T1 = *(const uint4*)(p + 256);
        if (bf & 4) T2 = *(const uint4*)(p + IMG * 256);
        if (bf & 8) T3 = *(const uint4*)(p + IMG * 256 + 256);
    }

#pragma unroll
    for (int i = 0; i < KPTS / 2; i++) {
        uint4 N0, N1, N2, N3;
        float nwx1 = 0.f, nwy1 = 0.f;
        N0 = N1 = N2 = N3 = make_uint4(0, 0, 0, 0);
        if (i < KPTS / 2 - 1) {
            int src = 2 * (i + 1) + half;
            int w0 = __shfl_sync(0xffffffffu, pt.x, src);
            int w1 = __shfl_sync(0xffffffffu, pt.y, src);
            int bf = w0 & 15;
            float2 w = __half22float2(uint_as_h2((unsigned)w1));
            nwx1 = w.x; nwy1 = w.y;
            const char* p = kvb + ((long)(w0 >> 4) << 8);
            if (bf & 1) N0 = *(const uint4*)(p);
            if (bf & 2) N1 = *(const uint4*)(p + 256);
            if (bf & 4) N2 = *(const uint4*)(p + IMG * 256);
            if (bf & 8) N3 = *(const uint4*)(p + IMG * 256 + 256);
        }

        float wx0 = 1.f - cwx1, wy0 = 1.f - cwy1;
        __half2 hw00 = __float2half2_rn(wx0  * wy0);
        __half2 hw01 = __float2half2_rn(cwx1 * wy0);
        __half2 hw10 = __float2half2_rn(wx0  * cwy1);
        __half2 hw11 = __float2half2_rn(cwx1 * cwy1);
        union { uint4 u; __half2 h2[4]; } A, B, C, D;
        A.u = T0; B.u = T1; C.u = T2; D.u = T3;
        __half2 hk0 = __hfma2(hw00, A.h2[0], __hfma2(hw01, B.h2[0],
                      __hfma2(hw10, C.h2[0], __hmul2(hw11, D.h2[0]))));
        __half2 hk1 = __hfma2(hw00, A.h2[1], __hfma2(hw01, B.h2[1],
                      __hfma2(hw10, C.h2[1], __hmul2(hw11, D.h2[1]))));
        __half2 hv0 = __hfma2(hw00, A.h2[2], __hfma2(hw01, B.h2[2],
                      __hfma2(hw10, C.h2[2], __hmul2(hw11, D.h2[2]))));
        __half2 hv1 = __hfma2(hw00, A.h2[3], __hfma2(hw01, B.h2[3],
                      __hfma2(hw10, C.h2[3], __hmul2(hw11, D.h2[3]))));

        __half2 d0h = __hfma2(Q0a, hk0, __hmul2(Q0b, hk1));
        __half2 d1h = __hfma2(Q1a, hk0, __hmul2(Q1b, hk1));
        __half2 d2h = __hfma2(Q2a, hk0, __hmul2(Q2b, hk1));
#pragma unroll
        for (int off = 8; off > 0; off >>= 1) {
            d0h = __hadd2(d0h, h2shflx(d0h, off));
            d1h = __hadd2(d1h, h2shflx(d1h, off));
            d2h = __hadd2(d2h, h2shflx(d2h, off));
        }
        float2 f0 = __half22float2(d0h);
        float2 f1 = __half22float2(d1h);
        float2 f2 = __half22float2(d2h);
        float e0 = __expf(f0.x + f0.y);
        float e1 = __expf(f1.x + f1.y);
        float e2 = __expf(f2.x + f2.y);
        s0v += e0; s1v += e1; s2v += e2;
        __half2 e0h = __float2half2_rn(e0);
        __half2 e1h = __float2half2_rn(e1);
        __half2 e2h = __float2half2_rn(e2);
        o0a = __hfma2(e0h, hv0, o0a); o0b = __hfma2(e0h, hv1, o0b);
        o1a = __hfma2(e1h, hv0, o1a); o1b = __hfma2(e1h, hv1, o1b);
        o2a = __hfma2(e2h, hv0, o2a); o2b = __hfma2(e2h, hv1, o2b);

        T0 = N0; T1 = N1; T2 = N2; T3 = N3;
        cwx1 = nwx1; cwy1 = nwy1;
    }

    o0a = __hadd2(o0a, h2shflx(o0a, 16)); o0b = __hadd2(o0b, h2shflx(o0b, 16));
    o1a = __hadd2(o1a, h2shflx(o1a, 16)); o1b = __hadd2(o1b, h2shflx(o1b, 16));
    o2a = __hadd2(o2a, h2shflx(o2a, 16)); o2b = __hadd2(o2b, h2shflx(o2b, 16));
    s0v += __shfl_xor_sync(0xffffffffu, s0v, 16);
    s1v += __shfl_xor_sync(0xffffffffu, s1v, 16);
    s2v += __shfl_xor_sync(0xffffffffu, s2v, 16);

    if (half == 0) {
        __half* orow = g_attn + (size_t)(g * 3) * AD + h * HDIM + l * 4;
        __half2 i0 = __float2half2_rn(1.f / s0v);
        __half2 i1 = __float2half2_rn(1.f / s1v);
        __half2 i2 = __float2half2_rn(1.f / s2v);
        uint2 st;
        st.x = h2_as_uint(__hmul2(o0a, i0)); st.y = h2_as_uint(__hmul2(o0b, i0));
        *(uint2*)(orow) = st;
        st.x = h2_as_uint(__hmul2(o1a, i1)); st.y = h2_as_uint(__hmul2(o1b, i1));
        *(uint2*)(orow + AD) = st;
        st.x = h2_as_uint(__hmul2(o2a, i2)); st.y = h2_as_uint(__hmul2(o2b, i2));
        *(uint2*)(orow + 2 * AD) = st;
    }
}

// ---------------------------------------------------------------------------
// K5: out = g_attn(fp16) @ Wout + b_out + feat, via tensor cores.
//   Block = 128 rows, 8 warps x 16 rows.  A frags loaded directly from
//   g_attn (already fp16 row-major).  B = Wout -> smem [n][k] fp16.
// ---------------------------------------------------------------------------
__global__ __launch_bounds__(256) void out_gemm(
    const float* __restrict__ Wout, const float* __restrict__ b_out,
    const float* __restrict__ feat, float* __restrict__ out)
{
    const int r0 = blockIdx.x * 128;
    __shared__ __half Bs[GFDIM][536];   // pad 536 -> bank stride 12, conflict-free
    const int t    = threadIdx.x;
    const int w    = t >> 5;
    const int lane = t & 31;
    const int qrow = lane >> 2;
    const int qk   = (lane & 3) * 2;

    // B: Wout[k][n] (512x32 fp32) -> Bs[n][k] fp16
#pragma unroll
    for (int rep = 0; rep < 16; rep++) {
        int idx = t + rep * 256;
        int k = idx >> 3, n4 = (idx & 7) * 4;
        float4 v = *(const float4*)(Wout + (size_t)k * GFDIM + n4);
        Bs[n4 + 0][k] = __float2half_rn(v.x);
        Bs[n4 + 1][k] = __float2half_rn(v.y);
        Bs[n4 + 2][k] = __float2half_rn(v.z);
        Bs[n4 + 3][k] = __float2half_rn(v.w);
    }
    __syncthreads();

    float acc[4][4];
#pragma unroll
    for (int j = 0; j < 4; j++)
#pragma unroll
        for (int f = 0; f < 4; f++) acc[j][f] = 0.f;

    const int rA = r0 + w * 16 + qrow;
    const __half* arow0 = g_attn + (size_t)rA * AD;
    const __half* arow1 = g_attn + (size_t)(rA + 8) * AD;

#pragma unroll 4
    for (int ks = 0; ks < 32; ks++) {
        int k0 = ks * 16;
        unsigned a0 = *(const unsigned*)(arow0 + k0 + qk);
        unsigned a1 = *(const unsigned*)(arow1 + k0 + qk);
        unsigned a2 = *(const unsigned*)(arow0 + k0 + qk + 8);
        unsigned a3 = *(const unsigned*)(arow1 + k0 + qk + 8);
#pragma unroll
        for (int j = 0; j < 4; j++) {
            int n = j * 8 + qrow;
            unsigned b0 = *(const unsigned*)&Bs[n][k0 + qk];
            unsigned b1 = *(const unsigned*)&Bs[n][k0 + qk + 8];
            mma16816(acc[j][0], acc[j][1], acc[j][2], acc[j][3],
                     a0, a1, a2, a3, b0, b1);
        }
    }

    const int colp = (lane & 3) * 2;
#pragma unroll
    for (int j = 0; j < 4; j++) {
        int col = j * 8 + colp;
        float b0 = b_out[col], b1 = b_out[col + 1];
        float2 f0 = *(const float2*)(feat + (size_t)rA * GFDIM + col);
        float2 f1 = *(const float2*)(feat + (size_t)(rA + 8) * GFDIM + col);
        *(float2*)(out + (size_t)rA * GFDIM + col) =
            make_float2(acc[j][0] + b0 + f0.x, acc[j][1] + b1 + f0.y);
        *(float2*)(out + (size_t)(rA + 8) * GFDIM + col) =
            make_float2(acc[j][2] + b0 + f1.x, acc[j][3] + b1 + f1.y);
    }
}

// ---------------------------------------------------------------------------
extern "C" void kernel_launch(void* const* d_in, const int* in_sizes, int n_in,
                              void* d_out, int out_size)
{
    const float* means      = (const float*)d_in[0];
    const float* scales     = (const float*)d_in[1];
    const float* rotations  = (const float*)d_in[2];
    const float* features   = (const float*)d_in[3];
    const float* transforms = (const float*)d_in[4];
    const float* projection = (const float*)d_in[5];
    const float* image_feat = (const float*)d_in[6];
    const float* Wq         = (const float*)d_in[7];
    const float* Wk         = (const float*)d_in[8];
    const float* Wv         = (const float*)d_in[9];
    const float* W_off      = (const float*)d_in[10];
    const float* b_off      = (const float*)d_in[11];
    const float* Wout       = (const float*)d_in[12];
    const float* b_out      = (const float*)d_in[13];
    float* out = (float*)d_out;

    kv_gemm<<<dim3(NPIX / 64, AD / 128), 256>>>(image_feat, Wk, Wv);
    q_gemm<<<G_N * 3 / 32, 256>>>(features, Wq);
    sigpp<<<NGH / 64, 256>>>(means, scales, rotations, transforms,
                             projection, W_off, b_off);
    gather_attn<<<G_N, 256>>>();
    out_gemm<<<G_N * 3 / 128, 256>>>(Wout, b_out, features, out);
}